// round 1
// baseline (speedup 1.0000x reference)
#include <cuda_runtime.h>

#define BB 4
#define NN 256
#define HH 8
#define DNI 32
#define DEI 16
#define DNO 32
#define DEO 32
#define HDNI 256
#define HDEI 128
#define HDNO 256
#define HDEO 256
#define TJ 64

// ---------------- scratch (no allocation allowed -> device globals) ----------------
__device__ float g_WT[HDNI * HDNO];     // [c][t]  = W_w[t][c]
__device__ float g_WodT[HDNI * HDNO];   // [c][t]  = Wod_w[t][c]
__device__ float g_WeT[HDEI * HDEO];    // [c][n]  = We_w[n][c]
__device__ float g_aeT[HDEI * HH];      // [c][h]  = ae_w[h][c]
__device__ float g_Wh[BB * NN * HDNO];
__device__ float g_od[BB * NN * HDNO];
__device__ float g_Whi[BB * NN * HH];
__device__ float g_Whj[BB * NN * HH];
__device__ float g_e[BB * HH * NN * NN];

// ---------------- f32x2 packed math helpers ----------------
__device__ __forceinline__ unsigned long long dup2(float x) {
    unsigned long long r;
    asm("mov.b64 %0, {%1, %1};" : "=l"(r) : "f"(x));
    return r;
}
#define FMA2(d, a, b) asm("fma.rn.f32x2 %0, %1, %2, %0;" : "+l"(d) : "l"(a), "l"(b))
#define UNPK(v, lo, hi) asm("mov.b64 {%0, %1}, %2;" : "=f"(lo), "=f"(hi) : "l"(v))

// ---------------- K0: transpose weights ----------------
__global__ __launch_bounds__(256) void k_transpose(
    const float* __restrict__ W_w, const float* __restrict__ Wod_w,
    const float* __restrict__ We_w, const float* __restrict__ ae_w)
{
    int i = blockIdx.x * blockDim.x + threadIdx.x;
    int stride = gridDim.x * blockDim.x;
    for (int idx = i; idx < 65536; idx += stride) {
        int c = idx >> 8, t = idx & 255;
        g_WT[idx] = W_w[t * 256 + c];
        g_WodT[idx] = Wod_w[t * 256 + c];
    }
    for (int idx = i; idx < 32768; idx += stride) {
        int c = idx >> 8, n = idx & 255;
        g_WeT[idx] = We_w[n * 128 + c];
    }
    for (int idx = i; idx < 1024; idx += stride) {
        int c = idx >> 3, h = idx & 7;
        g_aeT[idx] = ae_w[h * 128 + c];
    }
}

// ---------------- K1: Wh, od, Whi, Whj ----------------
__global__ __launch_bounds__(256) void k_node(
    const float* __restrict__ node_fea,
    const float* __restrict__ W_b, const float* __restrict__ Wod_b,
    const float* __restrict__ a1_w, const float* __restrict__ a2_w)
{
    __shared__ float nf_s[8][256];
    __shared__ float wh_s[8][256];
    int t = threadIdx.x;
    int b = blockIdx.y;
    int i0 = blockIdx.x * 8;

    for (int x = t; x < 8 * 256; x += 256) {
        int r = x >> 8, c = x & 255;
        int h = c >> 5, d = c & 31;
        nf_s[r][c] = node_fea[((b * HH + h) * NN + (i0 + r)) * DNI + d];
    }
    __syncthreads();

    float wh[8], odv[8];
    float wb = W_b[t], wob = Wod_b[t];
#pragma unroll
    for (int r = 0; r < 8; ++r) { wh[r] = wb; odv[r] = wob; }

#pragma unroll 4
    for (int c = 0; c < 256; ++c) {
        float wt = g_WT[c * 256 + t];
        float wo = g_WodT[c * 256 + t];
#pragma unroll
        for (int r = 0; r < 8; ++r) {
            float nv = nf_s[r][c];
            wh[r] = fmaf(nv, wt, wh[r]);
            odv[r] = fmaf(nv, wo, odv[r]);
        }
    }
#pragma unroll
    for (int r = 0; r < 8; ++r) {
        int row = b * NN + i0 + r;
        g_Wh[row * 256 + t] = wh[r];
        g_od[row * 256 + t] = odv[r];
        wh_s[r][t] = wh[r];
    }
    __syncthreads();

    int wid = t >> 5, lane = t & 31;  // warp wid -> head h = wid
#pragma unroll 1
    for (int r = 0; r < 8; ++r) {
        float s1 = 0.f, s2 = 0.f;
#pragma unroll
        for (int k = 0; k < 8; ++k) {
            int c = lane + k * 32;
            float wv = wh_s[r][c];
            s1 = fmaf(wv, a1_w[wid * 256 + c], s1);
            s2 = fmaf(wv, a2_w[wid * 256 + c], s2);
        }
#pragma unroll
        for (int off = 16; off; off >>= 1) {
            s1 += __shfl_down_sync(0xffffffffu, s1, off);
            s2 += __shfl_down_sync(0xffffffffu, s2, off);
        }
        if (lane == 0) {
            int row = b * NN + i0 + r;
            g_Whi[row * 8 + wid] = s1;
            g_Whj[row * 8 + wid] = s2;
        }
    }
}

// ---------------- K2: edge GEMM + attention logits ----------------
// dyn smem: s_wt[128*256] | s_ef[64*133] | s_ae[1024] | s_oib[256] | s_whi[8] | s_whj[512]
#define EDGE_SMEM_FLOATS (128 * 256 + 64 * 133 + 1024 + 256 + 8 + 512)
#define EDGE_SMEM_BYTES (EDGE_SMEM_FLOATS * 4)

__global__ __launch_bounds__(256, 1) void k_edge(
    const float* __restrict__ edge_fea, const int* __restrict__ adj,
    const float* __restrict__ ae_b, const float* __restrict__ We_b,
    float* __restrict__ edge_out)
{
    extern __shared__ float smemf[];
    float* s_wt = smemf;                  // [128][256]
    float* s_ef = s_wt + 128 * 256;       // [64][133]
    float* s_ae = s_ef + 64 * 133;        // [128][8]
    float* s_oib = s_ae + 1024;           // [256]
    float* s_whi = s_oib + 256;           // [8]
    float* s_whj = s_whi + 8;             // [64][8]

    int t = threadIdx.x;
    int j0 = blockIdx.x * TJ;
    int i = blockIdx.y;
    int b = blockIdx.z;

    // weights (vectorized copy)
    for (int x = t; x < 128 * 256 / 4; x += 256)
        reinterpret_cast<float4*>(s_wt)[x] = reinterpret_cast<const float4*>(g_WeT)[x];
    for (int x = t; x < 1024; x += 256) s_ae[x] = g_aeT[x];
    s_oib[t] = g_od[(b * NN + i) * 256 + t] + We_b[t];
    if (t < 8) s_whi[t] = g_Whi[(b * NN + i) * 8 + t];
    for (int x = t; x < TJ * 8; x += 256) {
        int jj = x >> 3, hh = x & 7;
        s_whj[x] = g_Whj[(b * NN + j0 + jj) * 8 + hh];
    }
    // ef tile: column c = h*16+d, rows padded to 133 floats
    for (int x = t; x < HH * TJ * DEI; x += 256) {
        int h = x >> 10;          // TJ*DEI = 1024
        int r = x & 1023;
        int jj = r >> 4, d = r & 15;
        s_ef[jj * 133 + h * 16 + d] =
            edge_fea[(((b * HH + h) * NN + i) * NN + (j0 + jj)) * DEI + d];
    }
    __syncthreads();

    // attention logits e[b,h,i,j] (512 tasks, conflict-free via 133 pad)
    for (int x = t; x < HH * TJ; x += 256) {
        int jj = x & 63, h = x >> 6;
        float acc = ae_b[h];
#pragma unroll 8
        for (int c = 0; c < 128; ++c)
            acc = fmaf(s_ef[jj * 133 + c], s_ae[c * 8 + h], acc);
        acc += s_whi[h] + s_whj[jj * 8 + h];
        acc = (acc > 0.f) ? acc : 0.2f * acc;        // leaky_relu(0.2)
        if (adj[(b * NN + i) * NN + j0 + jj] <= 0) acc = -9e15f;
        g_e[((b * HH + h) * NN + i) * NN + j0 + jj] = acc;
    }

    // main GEMM: [64 j, 128 k] x [128 k, 256 n], f32x2 packed, 8x8 thread tile
    int tm = t >> 5, tn = t & 31;
    unsigned long long acc[8][4];
#pragma unroll
    for (int r = 0; r < 8; ++r)
#pragma unroll
        for (int p = 0; p < 4; ++p) acc[r][p] = 0ull;

    const float* efrow = s_ef + (tm * 8) * 133;
#pragma unroll 4
    for (int k = 0; k < 128; ++k) {
        const ulonglong2* bp =
            reinterpret_cast<const ulonglong2*>(s_wt + (k << 8) + (tn << 3));
        ulonglong2 v0 = bp[0];
        ulonglong2 v1 = bp[1];
#pragma unroll
        for (int r = 0; r < 8; ++r) {
            unsigned long long aa = dup2(efrow[r * 133 + k]);
            FMA2(acc[r][0], aa, v0.x);
            FMA2(acc[r][1], aa, v0.y);
            FMA2(acc[r][2], aa, v1.x);
            FMA2(acc[r][3], aa, v1.y);
        }
    }

    // epilogue: + od_i + We_b (s_oib) + od_j, scatter to [B,H,N,N,32]
    int h = tn >> 2, dd = (tn & 3) << 3;
    const float4* obp = reinterpret_cast<const float4*>(s_oib + (tn << 3));
    float4 ob0 = obp[0], ob1 = obp[1];
#pragma unroll
    for (int r = 0; r < 8; ++r) {
        int j = j0 + tm * 8 + r;
        const float4* ojp =
            reinterpret_cast<const float4*>(g_od + (b * NN + j) * 256 + (tn << 3));
        float4 o0 = ojp[0], o1 = ojp[1];
        float4 w0, w1;
        UNPK(acc[r][0], w0.x, w0.y);
        UNPK(acc[r][1], w0.z, w0.w);
        UNPK(acc[r][2], w1.x, w1.y);
        UNPK(acc[r][3], w1.z, w1.w);
        w0.x += ob0.x + o0.x; w0.y += ob0.y + o0.y;
        w0.z += ob0.z + o0.z; w0.w += ob0.w + o0.w;
        w1.x += ob1.x + o1.x; w1.y += ob1.y + o1.y;
        w1.z += ob1.z + o1.z; w1.w += ob1.w + o1.w;
        float* dst = edge_out + ((((b * HH + h) * NN + i) * NN + j) << 5) + dd;
        *reinterpret_cast<float4*>(dst) = w0;
        *reinterpret_cast<float4*>(dst + 4) = w1;
    }
}

// ---------------- K3: softmax over j + node_new = att@Whh + Whh ----------------
__global__ __launch_bounds__(256) void k_attn(float* __restrict__ node_out)
{
    __shared__ float Whs[256][32];
    __shared__ float att[256];
    __shared__ float red[8][32];
    __shared__ float rbuf[8];
    __shared__ float s_mx, s_sum;

    int t = threadIdx.x;
    int h = blockIdx.y, b = blockIdx.z;
    int i0 = blockIdx.x * 32;

    for (int x = t; x < 256 * 32; x += 256) {
        int j = x >> 5, d = x & 31;
        Whs[j][d] = g_Wh[(b * NN + j) * 256 + h * 32 + d];
    }
    __syncthreads();

    int lane = t & 31, wid = t >> 5;
    for (int il = 0; il < 32; ++il) {
        int i = i0 + il;
        float ev = g_e[((b * HH + h) * NN + i) * NN + t];
        float v = ev;
#pragma unroll
        for (int off = 16; off; off >>= 1)
            v = fmaxf(v, __shfl_xor_sync(0xffffffffu, v, off));
        if (lane == 0) rbuf[wid] = v;
        __syncthreads();
        if (t == 0) {
            float m = rbuf[0];
            for (int w = 1; w < 8; ++w) m = fmaxf(m, rbuf[w]);
            s_mx = m;
        }
        __syncthreads();
        float p = __expf(ev - s_mx);
        float sv = p;
#pragma unroll
        for (int off = 16; off; off >>= 1)
            sv += __shfl_xor_sync(0xffffffffu, sv, off);
        if (lane == 0) rbuf[wid] = sv;
        __syncthreads();
        if (t == 0) {
            float s = 0.f;
            for (int w = 0; w < 8; ++w) s += rbuf[w];
            s_sum = 1.0f / s;
        }
        __syncthreads();
        att[t] = p * s_sum;
        __syncthreads();

        int d = t & 31, g = t >> 5;
        float part = 0.f;
#pragma unroll 8
        for (int jj = 0; jj < 32; ++jj)
            part = fmaf(att[g * 32 + jj], Whs[g * 32 + jj][d], part);
        red[g][d] = part;
        __syncthreads();
        if (t < 32) {
            float s = Whs[i][t];
#pragma unroll
            for (int g2 = 0; g2 < 8; ++g2) s += red[g2][t];
            node_out[((b * HH + h) * NN + i) * DNO + t] = s;
        }
        __syncthreads();
    }
}

// ---------------- launch ----------------
extern "C" void kernel_launch(void* const* d_in, const int* in_sizes, int n_in,
                              void* d_out, int out_size)
{
    const float* node_fea = (const float*)d_in[0];
    const float* edge_fea = (const float*)d_in[1];
    const int* adj = (const int*)d_in[2];
    const float* W_w = (const float*)d_in[3];
    const float* W_b = (const float*)d_in[4];
    const float* a1_w = (const float*)d_in[5];
    const float* a2_w = (const float*)d_in[6];
    const float* ae_w = (const float*)d_in[7];
    const float* ae_b = (const float*)d_in[8];
    const float* We_w = (const float*)d_in[9];
    const float* We_b = (const float*)d_in[10];
    const float* Wod_w = (const float*)d_in[11];
    const float* Wod_b = (const float*)d_in[12];

    float* out = (float*)d_out;
    float* node_out = out;                          // [B,H,N,DNO] first
    float* edge_out = out + BB * HH * NN * DNO;     // then [B,H,N,N,DEO]

    cudaFuncSetAttribute(k_edge, cudaFuncAttributeMaxDynamicSharedMemorySize,
                         EDGE_SMEM_BYTES);

    k_transpose<<<128, 256>>>(W_w, Wod_w, We_w, ae_w);
    k_node<<<dim3(32, BB), 256>>>(node_fea, W_b, Wod_b, a1_w, a2_w);
    k_edge<<<dim3(NN / TJ, NN, BB), 256, EDGE_SMEM_BYTES>>>(edge_fea, adj, ae_b,
                                                            We_b, edge_out);
    k_attn<<<dim3(NN / 32, HH, BB), 256>>>(node_out);
}

// round 3
// speedup vs baseline: 2.4292x; 2.4292x over previous
#include <cuda_runtime.h>
#include <cstdint>

#define BB 4
#define NN 256
#define HH 8

// ---------------- scratch ----------------
__device__ float g_WT[256 * 256];
__device__ float g_WodT[256 * 256];
__device__ float g_Wh[BB * NN * 256];
__device__ float g_od[BB * NN * 256];
__device__ float g_Whi[BB * NN * HH];
__device__ float g_Whj[BB * NN * HH];
__device__ float g_e[BB * HH * NN * NN];

__device__ __forceinline__ uint32_t to_tf32(float f) {
    uint32_t r;
    asm("cvt.rna.tf32.f32 %0, %1;" : "=r"(r) : "f"(f));
    return r;
}
__device__ __forceinline__ void mma8(float* c, uint32_t a0, uint32_t a1,
                                     uint32_t a2, uint32_t a3,
                                     uint32_t b0, uint32_t b1) {
    asm volatile(
        "mma.sync.aligned.m16n8k8.row.col.f32.tf32.tf32.f32 "
        "{%0,%1,%2,%3},{%4,%5,%6,%7},{%8,%9},{%0,%1,%2,%3};"
        : "+f"(c[0]), "+f"(c[1]), "+f"(c[2]), "+f"(c[3])
        : "r"(a0), "r"(a1), "r"(a2), "r"(a3), "r"(b0), "r"(b1));
}

// ---------------- K0: transpose weights for k_node ----------------
__global__ __launch_bounds__(256) void k_transpose(
    const float* __restrict__ W_w, const float* __restrict__ Wod_w)
{
    int i = blockIdx.x * blockDim.x + threadIdx.x;
    int stride = gridDim.x * blockDim.x;
    for (int idx = i; idx < 65536; idx += stride) {
        int c = idx >> 8, t = idx & 255;
        g_WT[idx] = W_w[t * 256 + c];
        g_WodT[idx] = Wod_w[t * 256 + c];
    }
}

// ---------------- K1: Wh, od, Whi, Whj ----------------
__global__ __launch_bounds__(256) void k_node(
    const float* __restrict__ node_fea,
    const float* __restrict__ W_b, const float* __restrict__ Wod_b,
    const float* __restrict__ a1_w, const float* __restrict__ a2_w)
{
    __shared__ float nf_s[8][256];
    __shared__ float wh_s[8][256];
    int t = threadIdx.x;
    int b = blockIdx.y;
    int i0 = blockIdx.x * 8;

    for (int x = t; x < 8 * 256; x += 256) {
        int r = x >> 8, c = x & 255;
        int h = c >> 5, d = c & 31;
        nf_s[r][c] = node_fea[((b * HH + h) * NN + (i0 + r)) * 32 + d];
    }
    __syncthreads();

    float wh[8], odv[8];
    float wb = W_b[t], wob = Wod_b[t];
#pragma unroll
    for (int r = 0; r < 8; ++r) { wh[r] = wb; odv[r] = wob; }

#pragma unroll 4
    for (int c = 0; c < 256; ++c) {
        float wt = g_WT[c * 256 + t];
        float wo = g_WodT[c * 256 + t];
#pragma unroll
        for (int r = 0; r < 8; ++r) {
            float nv = nf_s[r][c];
            wh[r] = fmaf(nv, wt, wh[r]);
            odv[r] = fmaf(nv, wo, odv[r]);
        }
    }
#pragma unroll
    for (int r = 0; r < 8; ++r) {
        int row = b * NN + i0 + r;
        g_Wh[row * 256 + t] = wh[r];
        g_od[row * 256 + t] = odv[r];
        wh_s[r][t] = wh[r];
    }
    __syncthreads();

    int wid = t >> 5, lane = t & 31;
#pragma unroll 1
    for (int r = 0; r < 8; ++r) {
        float s1 = 0.f, s2 = 0.f;
#pragma unroll
        for (int k = 0; k < 8; ++k) {
            int c = lane + k * 32;
            float wv = wh_s[r][c];
            s1 = fmaf(wv, a1_w[wid * 256 + c], s1);
            s2 = fmaf(wv, a2_w[wid * 256 + c], s2);
        }
#pragma unroll
        for (int off = 16; off; off >>= 1) {
            s1 += __shfl_down_sync(0xffffffffu, s1, off);
            s2 += __shfl_down_sync(0xffffffffu, s2, off);
        }
        if (lane == 0) {
            int row = b * NN + i0 + r;
            g_Whi[row * 8 + wid] = s1;
            g_Whj[row * 8 + wid] = s2;
        }
    }
}

// ---------------- K2: mma.sync tf32 edge kernel ----------------
// smem floats: s_oib[2][256] | sA 16*8*32*4 | sB 16*33*32*2
#define SOFF_OIB 0
#define SOFF_A 512
#define SOFF_B (512 + 16384)
#define EDGE_SMEM_FLOATS (512 + 16384 + 33792)
#define EDGE_SMEM (EDGE_SMEM_FLOATS * 4)

__global__ __launch_bounds__(256, 1) void k_edge_mma(
    const float* __restrict__ edge_fea, const int* __restrict__ adj,
    const float* __restrict__ ae_w, const float* __restrict__ ae_b,
    const float* __restrict__ We_w, const float* __restrict__ We_b,
    float* __restrict__ edge_out)
{
    extern __shared__ float sf[];
    float* s_oib = sf + SOFF_OIB;
    uint4* sA = reinterpret_cast<uint4*>(sf + SOFF_A);
    uint2* sB = reinterpret_cast<uint2*>(sf + SOFF_B);

    int t = threadIdx.x;
    int w = t >> 5, lane = t & 31;
    int mg = w >> 2, ng = w & 3;
    int lr = lane >> 2, lc = lane & 3;

    // ---- pack B (once): We_w[256n][128k] + ae_w[8][128] as extra n-tile 32
    for (int x = t; x < 16896; x += 256) {
        int ln = x & 31;
        int nt = (x >> 5) % 33;
        int s = x / (33 * 32);
        int kin = ln & 3;
        int k = s * 8 + kin;
        float b0, b1;
        if (nt < 32) {
            int n = nt * 8 + (ln >> 2);
            b0 = We_w[n * 128 + k];
            b1 = We_w[n * 128 + k + 4];
        } else {
            int hp = ln >> 2;
            b0 = ae_w[hp * 128 + k];
            b1 = ae_w[hp * 128 + k + 4];
        }
        uint2 pk;
        pk.x = to_tf32(b0);
        pk.y = to_tf32(b1);
        sB[(s * 33 + nt) * 32 + ln] = pk;
    }
    __syncthreads();

    int pc = 0;
    for (int u = blockIdx.x; u < 2048; u += gridDim.x, ++pc) {
        int b = u >> 9, i = (u >> 1) & 255, j0 = (u & 1) << 7;
        int buf = (pc & 1) << 8;

        // ---- pack A: gather 4 scattered gmem floats -> one STS.128 per item
        {
            int mt = t >> 5;          // warp id = m-tile
            int jr1 = j0 + mt * 16 + lr;
            int jr2 = jr1 + 8;
#pragma unroll
            for (int s = 0; s < 16; ++s) {
                int h = s >> 1;
                int d = ((s & 1) << 3) + lc;
                int eb = ((b * 8 + h) * NN + i) * NN;
                float v0 = edge_fea[(eb + jr1) * 16 + d];
                float v1 = edge_fea[(eb + jr2) * 16 + d];
                float v2 = edge_fea[(eb + jr1) * 16 + d + 4];
                float v3 = edge_fea[(eb + jr2) * 16 + d + 4];
                uint4 pk;
                pk.x = to_tf32(v0);
                pk.y = to_tf32(v1);
                pk.z = to_tf32(v2);
                pk.w = to_tf32(v3);
                sA[(s * 8 + mt) * 32 + lane] = pk;
            }
            s_oib[buf + t] = g_od[(b * NN + i) * 256 + t] + We_b[t];
        }
        __syncthreads();

        // ---- mainloop
        float c[4][9][4];
#pragma unroll
        for (int a = 0; a < 4; ++a)
#pragma unroll
            for (int n = 0; n < 9; ++n)
#pragma unroll
                for (int q = 0; q < 4; ++q) c[a][n][q] = 0.f;

#pragma unroll
        for (int s = 0; s < 16; ++s) {
            uint4 A[4];
#pragma unroll
            for (int m = 0; m < 4; ++m)
                A[m] = sA[(s * 8 + mg * 4 + m) * 32 + lane];
            uint2 Bv[9];
#pragma unroll
            for (int n = 0; n < 8; ++n)
                Bv[n] = sB[(s * 33 + ng * 8 + n) * 32 + lane];
            if (ng == 0) Bv[8] = sB[(s * 33 + 32) * 32 + lane];
#pragma unroll
            for (int m = 0; m < 4; ++m) {
#pragma unroll
                for (int n = 0; n < 8; ++n)
                    mma8(c[m][n], A[m].x, A[m].y, A[m].z, A[m].w,
                         Bv[n].x, Bv[n].y);
            }
            if (ng == 0) {
#pragma unroll
                for (int m = 0; m < 4; ++m)
                    mma8(c[m][8], A[m].x, A[m].y, A[m].z, A[m].w,
                         Bv[8].x, Bv[8].y);
            }
        }
        __syncthreads();

        // ---- epilogue: logits (ng==0) then edge stores
        if (ng == 0) {
            int hp = lc * 2;
            float2 whi = *reinterpret_cast<const float2*>(
                g_Whi + (b * NN + i) * 8 + hp);
            float2 aeb = *reinterpret_cast<const float2*>(ae_b + hp);
            float bi0 = whi.x + aeb.x, bi1 = whi.y + aeb.y;
            const int* adjrow = adj + (b * NN + i) * NN;
#pragma unroll
            for (int m = 0; m < 4; ++m) {
                int jg = j0 + mg * 64 + m * 16 + lr;
#pragma unroll
                for (int half = 0; half < 2; ++half) {
                    int row = jg + half * 8;
                    float2 whj = *reinterpret_cast<const float2*>(
                        g_Whj + (b * NN + row) * 8 + hp);
                    int av = adjrow[row];
                    float e0 = c[m][8][half * 2] + bi0 + whj.x;
                    float e1 = c[m][8][half * 2 + 1] + bi1 + whj.y;
                    e0 = (e0 > 0.f) ? e0 : 0.2f * e0;
                    e1 = (e1 > 0.f) ? e1 : 0.2f * e1;
                    if (av <= 0) { e0 = -9e15f; e1 = -9e15f; }
                    g_e[((b * 8 + hp) * NN + i) * NN + row] = e0;
                    g_e[((b * 8 + hp + 1) * NN + i) * NN + row] = e1;
                }
            }
        }

        const float* oib = s_oib + buf;
#pragma unroll
        for (int n = 0; n < 8; ++n) {
            int n0 = ng * 64 + n * 8;
            int h = n0 >> 5;
            int dd = (n0 & 31) + lc * 2;
            float2 ob = *reinterpret_cast<const float2*>(oib + n0 + lc * 2);
            int base = ((b * 8 + h) * NN + i) * NN;
#pragma unroll
            for (int m = 0; m < 4; ++m) {
                int jg = j0 + mg * 64 + m * 16 + lr;
                float2 od0 = *reinterpret_cast<const float2*>(
                    g_od + (b * NN + jg) * 256 + n0 + lc * 2);
                float2 od1 = *reinterpret_cast<const float2*>(
                    g_od + (b * NN + jg + 8) * 256 + n0 + lc * 2);
                float2 o0, o1;
                o0.x = c[m][n][0] + ob.x + od0.x;
                o0.y = c[m][n][1] + ob.y + od0.y;
                o1.x = c[m][n][2] + ob.x + od1.x;
                o1.y = c[m][n][3] + ob.y + od1.y;
                *reinterpret_cast<float2*>(edge_out + (base + jg) * 32 + dd) = o0;
                *reinterpret_cast<float2*>(edge_out + (base + jg + 8) * 32 + dd) = o1;
            }
        }
    }
}

// ---------------- K3: softmax + node_new (warp-autonomous) ----------------
__global__ __launch_bounds__(256) void k_attn2(float* __restrict__ node_out)
{
    extern __shared__ float sm2[];
    float* Whs = sm2;           // [256][32]
    float* att = sm2 + 8192;    // [32][256]
    int t = threadIdx.x, w = t >> 5, lane = t & 31;
    int i0 = blockIdx.x << 5, h = blockIdx.y, b = blockIdx.z;

    float4* Wh4 = reinterpret_cast<float4*>(Whs);
    const float4* g4 = reinterpret_cast<const float4*>(g_Wh);
    for (int x = t; x < 2048; x += 256) {
        int j = x >> 3, dq = x & 7;
        Wh4[x] = g4[(b * NN + j) * 64 + (h << 3) + dq];
    }
    __syncthreads();

    const float4* e4 = reinterpret_cast<const float4*>(g_e);
#pragma unroll
    for (int r = 0; r < 4; ++r) {
        int il = w + (r << 3);
        int i = i0 + il;
        int idx = (((b << 3) + h) * NN + i) * 64 + (lane << 1);
        float4 x0 = e4[idx], x1 = e4[idx + 1];
        float mx = fmaxf(fmaxf(fmaxf(x0.x, x0.y), fmaxf(x0.z, x0.w)),
                         fmaxf(fmaxf(x1.x, x1.y), fmaxf(x1.z, x1.w)));
#pragma unroll
        for (int o = 16; o; o >>= 1)
            mx = fmaxf(mx, __shfl_xor_sync(0xffffffffu, mx, o));
        float p0 = __expf(x0.x - mx), p1 = __expf(x0.y - mx);
        float p2 = __expf(x0.z - mx), p3 = __expf(x0.w - mx);
        float p4 = __expf(x1.x - mx), p5 = __expf(x1.y - mx);
        float p6 = __expf(x1.z - mx), p7 = __expf(x1.w - mx);
        float s = ((p0 + p1) + (p2 + p3)) + ((p4 + p5) + (p6 + p7));
#pragma unroll
        for (int o = 16; o; o >>= 1)
            s += __shfl_xor_sync(0xffffffffu, s, o);
        float rinv = 1.0f / s;
        float4 y0 = {p0 * rinv, p1 * rinv, p2 * rinv, p3 * rinv};
        float4 y1 = {p4 * rinv, p5 * rinv, p6 * rinv, p7 * rinv};
        float4* arow = reinterpret_cast<float4*>(att + il * 256);
        arow[lane * 2] = y0;
        arow[lane * 2 + 1] = y1;
    }
    __syncwarp();

    float acc0 = 0.f, acc1 = 0.f, acc2 = 0.f, acc3 = 0.f;
    const float4* a0 = reinterpret_cast<const float4*>(att + w * 256);
    const float4* a1 = reinterpret_cast<const float4*>(att + (w + 8) * 256);
    const float4* a2 = reinterpret_cast<const float4*>(att + (w + 16) * 256);
    const float4* a3 = reinterpret_cast<const float4*>(att + (w + 24) * 256);
#pragma unroll 4
    for (int jq = 0; jq < 64; ++jq) {
        int j = jq << 2;
        float w0 = Whs[j * 32 + lane];
        float w1 = Whs[(j + 1) * 32 + lane];
        float w2 = Whs[(j + 2) * 32 + lane];
        float w3 = Whs[(j + 3) * 32 + lane];
        float4 q;
        q = a0[jq]; acc0 += q.x * w0 + q.y * w1 + q.z * w2 + q.w * w3;
        q = a1[jq]; acc1 += q.x * w0 + q.y * w1 + q.z * w2 + q.w * w3;
        q = a2[jq]; acc2 += q.x * w0 + q.y * w1 + q.z * w2 + q.w * w3;
        q = a3[jq]; acc3 += q.x * w0 + q.y * w1 + q.z * w2 + q.w * w3;
    }
    float accs[4] = {acc0, acc1, acc2, acc3};
#pragma unroll
    for (int r = 0; r < 4; ++r) {
        int i = i0 + w + (r << 3);
        node_out[(((b << 3) + h) * NN + i) * 32 + lane] =
            accs[r] + Whs[i * 32 + lane];
    }
}

// ---------------- launch ----------------
extern "C" void kernel_launch(void* const* d_in, const int* in_sizes, int n_in,
                              void* d_out, int out_size)
{
    const float* node_fea = (const float*)d_in[0];
    const float* edge_fea = (const float*)d_in[1];
    const int* adj = (const int*)d_in[2];
    const float* W_w = (const float*)d_in[3];
    const float* W_b = (const float*)d_in[4];
    const float* a1_w = (const float*)d_in[5];
    const float* a2_w = (const float*)d_in[6];
    const float* ae_w = (const float*)d_in[7];
    const float* ae_b = (const float*)d_in[8];
    const float* We_w = (const float*)d_in[9];
    const float* We_b = (const float*)d_in[10];
    const float* Wod_w = (const float*)d_in[11];
    const float* Wod_b = (const float*)d_in[12];

    float* out = (float*)d_out;
    float* node_out = out;                       // [B,H,N,DNO]
    float* edge_out = out + BB * HH * NN * 32;   // [B,H,N,N,DEO]

    cudaFuncSetAttribute(k_edge_mma, cudaFuncAttributeMaxDynamicSharedMemorySize,
                         EDGE_SMEM);
    cudaFuncSetAttribute(k_attn2, cudaFuncAttributeMaxDynamicSharedMemorySize,
                         65536);

    k_transpose<<<128, 256>>>(W_w, Wod_w);
    k_node<<<dim3(32, BB), 256>>>(node_fea, W_b, Wod_b, a1_w, a2_w);
    k_edge_mma<<<152, 256, EDGE_SMEM>>>(edge_fea, adj, ae_w, ae_b, We_w, We_b,
                                        edge_out);
    k_attn2<<<dim3(8, HH, BB), 256, 65536>>>(node_out);
}

// round 4
// speedup vs baseline: 2.5691x; 1.0576x over previous
#include <cuda_runtime.h>
#include <cstdint>

#define BB 4
#define NN 256
#define HH 8

// ---------------- scratch ----------------
__device__ float g_WT[256 * 256];
__device__ float g_WodT[256 * 256];
__device__ float g_Wh[BB * NN * 256];
__device__ float g_od[BB * NN * 256];
__device__ float g_Whi[BB * NN * HH];
__device__ float g_Whj[BB * NN * HH];
__device__ float g_e[BB * HH * NN * NN];

__device__ __forceinline__ uint32_t to_tf32(float f) {
    uint32_t r;
    asm("cvt.rna.tf32.f32 %0, %1;" : "=r"(r) : "f"(f));
    return r;
}
__device__ __forceinline__ uint32_t smem_u32(const void* p) {
    uint32_t a;
    asm("{ .reg .u64 t; cvta.to.shared.u64 t, %1; cvt.u32.u64 %0, t; }"
        : "=r"(a) : "l"(p));
    return a;
}
__device__ __forceinline__ void mma8(float* c, uint32_t a0, uint32_t a1,
                                     uint32_t a2, uint32_t a3,
                                     uint32_t b0, uint32_t b1) {
    asm volatile(
        "mma.sync.aligned.m16n8k8.row.col.f32.tf32.tf32.f32 "
        "{%0,%1,%2,%3},{%4,%5,%6,%7},{%8,%9},{%0,%1,%2,%3};"
        : "+f"(c[0]), "+f"(c[1]), "+f"(c[2]), "+f"(c[3])
        : "r"(a0), "r"(a1), "r"(a2), "r"(a3), "r"(b0), "r"(b1));
}
#define CP_ASYNC16(dst, src) \
    asm volatile("cp.async.cg.shared.global [%0], [%1], 16;" \
                 :: "r"(dst), "l"(src))
#define CP_COMMIT() asm volatile("cp.async.commit_group;" ::: "memory")
#define CP_WAIT0() asm volatile("cp.async.wait_group 0;" ::: "memory")

// ---------------- K0: transpose weights for k_node ----------------
__global__ __launch_bounds__(256) void k_transpose(
    const float* __restrict__ W_w, const float* __restrict__ Wod_w)
{
    int i = blockIdx.x * blockDim.x + threadIdx.x;
    int stride = gridDim.x * blockDim.x;
    for (int idx = i; idx < 65536; idx += stride) {
        int c = idx >> 8, t = idx & 255;
        g_WT[idx] = W_w[t * 256 + c];
        g_WodT[idx] = Wod_w[t * 256 + c];
    }
}

// ---------------- K1: Wh, od, Whi, Whj ----------------
__global__ __launch_bounds__(256) void k_node(
    const float* __restrict__ node_fea,
    const float* __restrict__ W_b, const float* __restrict__ Wod_b,
    const float* __restrict__ a1_w, const float* __restrict__ a2_w)
{
    __shared__ float nf_s[8][256];
    __shared__ float wh_s[8][256];
    int t = threadIdx.x;
    int b = blockIdx.y;
    int i0 = blockIdx.x * 8;

    for (int x = t; x < 8 * 256; x += 256) {
        int r = x >> 8, c = x & 255;
        int h = c >> 5, d = c & 31;
        nf_s[r][c] = node_fea[((b * HH + h) * NN + (i0 + r)) * 32 + d];
    }
    __syncthreads();

    float wh[8], odv[8];
    float wb = W_b[t], wob = Wod_b[t];
#pragma unroll
    for (int r = 0; r < 8; ++r) { wh[r] = wb; odv[r] = wob; }

#pragma unroll 4
    for (int c = 0; c < 256; ++c) {
        float wt = g_WT[c * 256 + t];
        float wo = g_WodT[c * 256 + t];
#pragma unroll
        for (int r = 0; r < 8; ++r) {
            float nv = nf_s[r][c];
            wh[r] = fmaf(nv, wt, wh[r]);
            odv[r] = fmaf(nv, wo, odv[r]);
        }
    }
#pragma unroll
    for (int r = 0; r < 8; ++r) {
        int row = b * NN + i0 + r;
        g_Wh[row * 256 + t] = wh[r];
        g_od[row * 256 + t] = odv[r];
        wh_s[r][t] = wh[r];
    }
    __syncthreads();

    int wid = t >> 5, lane = t & 31;
#pragma unroll 1
    for (int r = 0; r < 8; ++r) {
        float s1 = 0.f, s2 = 0.f;
#pragma unroll
        for (int k = 0; k < 8; ++k) {
            int c = lane + k * 32;
            float wv = wh_s[r][c];
            s1 = fmaf(wv, a1_w[wid * 256 + c], s1);
            s2 = fmaf(wv, a2_w[wid * 256 + c], s2);
        }
#pragma unroll
        for (int off = 16; off; off >>= 1) {
            s1 += __shfl_down_sync(0xffffffffu, s1, off);
            s2 += __shfl_down_sync(0xffffffffu, s2, off);
        }
        if (lane == 0) {
            int row = b * NN + i0 + r;
            g_Whi[row * 8 + wid] = s1;
            g_Whj[row * 8 + wid] = s2;
        }
    }
}

// ---------------- K2: mma.sync tf32 edge kernel (cp.async pipelined) ----------------
// smem floats: s_oib[2][256] | sA[128][132] raw fp32 | sB frag 16896 uint2
#define SOFF_A 512
#define SOFF_B (512 + 16896)
#define EDGE_SMEM_FLOATS (512 + 16896 + 33792)
#define EDGE_SMEM (EDGE_SMEM_FLOATS * 4)

__global__ __launch_bounds__(256, 1) void k_edge_mma(
    const float* __restrict__ edge_fea, const int* __restrict__ adj,
    const float* __restrict__ ae_w, const float* __restrict__ ae_b,
    const float* __restrict__ We_w, const float* __restrict__ We_b,
    float* __restrict__ edge_out)
{
    extern __shared__ float sf[];
    float* s_oib = sf;
    float* sA = sf + SOFF_A;
    uint2* sB = reinterpret_cast<uint2*>(sf + SOFF_B);
    uint32_t sA_u = smem_u32(sA);

    int t = threadIdx.x;
    int w = t >> 5, lane = t & 31;
    int mg = w >> 2, ng = w & 3;
    int lr = lane >> 2, lc = lane & 3;

    // ---- issue A cp.async for a tile: 16 x 16B chunks per thread
    auto issue_A = [&](int u) {
        int b = u >> 9, i = (u >> 1) & 255, j0 = (u & 1) << 7;
#pragma unroll
        for (int cch = 0; cch < 16; ++cch) {
            int g = (cch << 8) + t;
            int h = g >> 9, r = g & 511, j = r >> 2, dq = r & 3;
            const float* src =
                edge_fea + ((((b * 8 + h) * NN + i) * NN) + j0 + j) * 16 + dq * 4;
            uint32_t dst = sA_u + (uint32_t)(j * 528 + h * 64 + dq * 16);
            CP_ASYNC16(dst, src);
        }
    };
    auto load_oib = [&](int u, int slot) {
        int b = u >> 9, i = (u >> 1) & 255;
        s_oib[slot * 256 + t] = g_od[(b * NN + i) * 256 + t] + We_b[t];
    };

    int u = blockIdx.x;
    issue_A(u);
    load_oib(u, 0);
    CP_COMMIT();

    // ---- pack B (once): We_w[256n][128k] + ae_w[8][128] as extra n-tile 32
    for (int x = t; x < 16896; x += 256) {
        int ln = x & 31;
        int nt = (x >> 5) % 33;
        int s = x / (33 * 32);
        int kin = ln & 3;
        int k = s * 8 + kin;
        float b0, b1;
        if (nt < 32) {
            int n = nt * 8 + (ln >> 2);
            b0 = We_w[n * 128 + k];
            b1 = We_w[n * 128 + k + 4];
        } else {
            int hp = ln >> 2;
            b0 = ae_w[hp * 128 + k];
            b1 = ae_w[hp * 128 + k + 4];
        }
        uint2 pk;
        pk.x = to_tf32(b0);
        pk.y = to_tf32(b1);
        sB[(s * 33 + nt) * 32 + ln] = pk;
    }

    int buf = 0;
    while (u < 2048) {
        CP_WAIT0();
        __syncthreads();
        int b = u >> 9, i = (u >> 1) & 255, j0 = (u & 1) << 7;

        // ---- mainloop: A raw-fp32-as-tf32 from sA, B frags from sB
        float c[4][8][4];
        float c8[4][4];
#pragma unroll
        for (int a = 0; a < 4; ++a) {
#pragma unroll
            for (int n = 0; n < 8; ++n)
#pragma unroll
                for (int q = 0; q < 4; ++q) c[a][n][q] = 0.f;
#pragma unroll
            for (int q = 0; q < 4; ++q) c8[a][q] = 0.f;
        }

        int ro1 = lr * 132, ro2 = ro1 + 8 * 132;
#pragma unroll
        for (int s = 0; s < 16; ++s) {
            int col = s * 8 + lc;
            uint32_t A[4][4];
#pragma unroll
            for (int m = 0; m < 4; ++m) {
                const float* ap = sA + (mg * 64 + m * 16) * 132 + col;
                A[m][0] = __float_as_uint(ap[ro1]);
                A[m][1] = __float_as_uint(ap[ro2]);
                A[m][2] = __float_as_uint(ap[ro1 + 4]);
                A[m][3] = __float_as_uint(ap[ro2 + 4]);
            }
            uint2 Bv[8];
#pragma unroll
            for (int n = 0; n < 8; ++n)
                Bv[n] = sB[(s * 33 + ng * 8 + n) * 32 + lane];
#pragma unroll
            for (int m = 0; m < 4; ++m)
#pragma unroll
                for (int n = 0; n < 8; ++n)
                    mma8(c[m][n], A[m][0], A[m][1], A[m][2], A[m][3],
                         Bv[n].x, Bv[n].y);
            if (ng == 0) {
                uint2 B8 = sB[(s * 33 + 32) * 32 + lane];
#pragma unroll
                for (int m = 0; m < 4; ++m)
                    mma8(c8[m], A[m][0], A[m][1], A[m][2], A[m][3], B8.x, B8.y);
            }
        }
        __syncthreads();

        // ---- prefetch next tile's A while epilogue runs
        int un = u + gridDim.x;
        if (un < 2048) {
            issue_A(un);
            load_oib(un, buf ^ 1);
        }
        CP_COMMIT();

        // ---- epilogue: logits (ng==0) then edge stores
        if (ng == 0) {
            int hp = lc * 2;
            float2 whi = *reinterpret_cast<const float2*>(
                g_Whi + (b * NN + i) * 8 + hp);
            float2 aeb = *reinterpret_cast<const float2*>(ae_b + hp);
            float bi0 = whi.x + aeb.x, bi1 = whi.y + aeb.y;
            const int* adjrow = adj + (b * NN + i) * NN;
#pragma unroll
            for (int m = 0; m < 4; ++m) {
                int jg = j0 + mg * 64 + m * 16 + lr;
#pragma unroll
                for (int half = 0; half < 2; ++half) {
                    int row = jg + half * 8;
                    float2 whj = *reinterpret_cast<const float2*>(
                        g_Whj + (b * NN + row) * 8 + hp);
                    int av = adjrow[row];
                    float e0 = c8[m][half * 2] + bi0 + whj.x;
                    float e1 = c8[m][half * 2 + 1] + bi1 + whj.y;
                    e0 = (e0 > 0.f) ? e0 : 0.2f * e0;
                    e1 = (e1 > 0.f) ? e1 : 0.2f * e1;
                    if (av <= 0) { e0 = -9e15f; e1 = -9e15f; }
                    g_e[((b * 8 + hp) * NN + i) * NN + row] = e0;
                    g_e[((b * 8 + hp + 1) * NN + i) * NN + row] = e1;
                }
            }
        }

        const float* oib = s_oib + buf * 256;
#pragma unroll
        for (int n = 0; n < 8; ++n) {
            int n0 = ng * 64 + n * 8;
            int h = n0 >> 5;
            int dd = (n0 & 31) + lc * 2;
            float2 ob = *reinterpret_cast<const float2*>(oib + n0 + lc * 2);
            int base = ((b * 8 + h) * NN + i) * NN;
#pragma unroll
            for (int m = 0; m < 4; ++m) {
                int jg = j0 + mg * 64 + m * 16 + lr;
                float2 od0 = *reinterpret_cast<const float2*>(
                    g_od + (b * NN + jg) * 256 + n0 + lc * 2);
                float2 od1 = *reinterpret_cast<const float2*>(
                    g_od + (b * NN + jg + 8) * 256 + n0 + lc * 2);
                float2 o0, o1;
                o0.x = c[m][n][0] + ob.x + od0.x;
                o0.y = c[m][n][1] + ob.y + od0.y;
                o1.x = c[m][n][2] + ob.x + od1.x;
                o1.y = c[m][n][3] + ob.y + od1.y;
                *reinterpret_cast<float2*>(edge_out + (base + jg) * 32 + dd) = o0;
                *reinterpret_cast<float2*>(edge_out + (base + jg + 8) * 32 + dd) = o1;
            }
        }
        u = un;
        buf ^= 1;
    }
}

// ---------------- K3: softmax + node_new (warp-autonomous) ----------------
__global__ __launch_bounds__(256) void k_attn2(float* __restrict__ node_out)
{
    extern __shared__ float sm2[];
    float* Whs = sm2;           // [256][32]
    float* att = sm2 + 8192;    // [32][256]
    int t = threadIdx.x, w = t >> 5, lane = t & 31;
    int i0 = blockIdx.x << 5, h = blockIdx.y, b = blockIdx.z;

    float4* Wh4 = reinterpret_cast<float4*>(Whs);
    const float4* g4 = reinterpret_cast<const float4*>(g_Wh);
    for (int x = t; x < 2048; x += 256) {
        int j = x >> 3, dq = x & 7;
        Wh4[x] = g4[(b * NN + j) * 64 + (h << 3) + dq];
    }
    __syncthreads();

    const float4* e4 = reinterpret_cast<const float4*>(g_e);
#pragma unroll
    for (int r = 0; r < 4; ++r) {
        int il = w + (r << 3);
        int i = i0 + il;
        int idx = (((b << 3) + h) * NN + i) * 64 + (lane << 1);
        float4 x0 = e4[idx], x1 = e4[idx + 1];
        float mx = fmaxf(fmaxf(fmaxf(x0.x, x0.y), fmaxf(x0.z, x0.w)),
                         fmaxf(fmaxf(x1.x, x1.y), fmaxf(x1.z, x1.w)));
#pragma unroll
        for (int o = 16; o; o >>= 1)
            mx = fmaxf(mx, __shfl_xor_sync(0xffffffffu, mx, o));
        float p0 = __expf(x0.x - mx), p1 = __expf(x0.y - mx);
        float p2 = __expf(x0.z - mx), p3 = __expf(x0.w - mx);
        float p4 = __expf(x1.x - mx), p5 = __expf(x1.y - mx);
        float p6 = __expf(x1.z - mx), p7 = __expf(x1.w - mx);
        float s = ((p0 + p1) + (p2 + p3)) + ((p4 + p5) + (p6 + p7));
#pragma unroll
        for (int o = 16; o; o >>= 1)
            s += __shfl_xor_sync(0xffffffffu, s, o);
        float rinv = 1.0f / s;
        float4 y0 = {p0 * rinv, p1 * rinv, p2 * rinv, p3 * rinv};
        float4 y1 = {p4 * rinv, p5 * rinv, p6 * rinv, p7 * rinv};
        float4* arow = reinterpret_cast<float4*>(att + il * 256);
        arow[lane * 2] = y0;
        arow[lane * 2 + 1] = y1;
    }
    __syncwarp();

    float acc0 = 0.f, acc1 = 0.f, acc2 = 0.f, acc3 = 0.f;
    const float4* a0 = reinterpret_cast<const float4*>(att + w * 256);
    const float4* a1 = reinterpret_cast<const float4*>(att + (w + 8) * 256);
    const float4* a2 = reinterpret_cast<const float4*>(att + (w + 16) * 256);
    const float4* a3 = reinterpret_cast<const float4*>(att + (w + 24) * 256);
#pragma unroll 4
    for (int jq = 0; jq < 64; ++jq) {
        int j = jq << 2;
        float w0 = Whs[j * 32 + lane];
        float w1 = Whs[(j + 1) * 32 + lane];
        float w2 = Whs[(j + 2) * 32 + lane];
        float w3 = Whs[(j + 3) * 32 + lane];
        float4 q;
        q = a0[jq]; acc0 += q.x * w0 + q.y * w1 + q.z * w2 + q.w * w3;
        q = a1[jq]; acc1 += q.x * w0 + q.y * w1 + q.z * w2 + q.w * w3;
        q = a2[jq]; acc2 += q.x * w0 + q.y * w1 + q.z * w2 + q.w * w3;
        q = a3[jq]; acc3 += q.x * w0 + q.y * w1 + q.z * w2 + q.w * w3;
    }
    float accs[4] = {acc0, acc1, acc2, acc3};
#pragma unroll
    for (int r = 0; r < 4; ++r) {
        int i = i0 + w + (r << 3);
        node_out[(((b << 3) + h) * NN + i) * 32 + lane] =
            accs[r] + Whs[i * 32 + lane];
    }
}

// ---------------- launch ----------------
extern "C" void kernel_launch(void* const* d_in, const int* in_sizes, int n_in,
                              void* d_out, int out_size)
{
    const float* node_fea = (const float*)d_in[0];
    const float* edge_fea = (const float*)d_in[1];
    const int* adj = (const int*)d_in[2];
    const float* W_w = (const float*)d_in[3];
    const float* W_b = (const float*)d_in[4];
    const float* a1_w = (const float*)d_in[5];
    const float* a2_w = (const float*)d_in[6];
    const float* ae_w = (const float*)d_in[7];
    const float* ae_b = (const float*)d_in[8];
    const float* We_w = (const float*)d_in[9];
    const float* We_b = (const float*)d_in[10];
    const float* Wod_w = (const float*)d_in[11];
    const float* Wod_b = (const float*)d_in[12];

    float* out = (float*)d_out;
    float* node_out = out;                       // [B,H,N,DNO]
    float* edge_out = out + BB * HH * NN * 32;   // [B,H,N,N,DEO]

    cudaFuncSetAttribute(k_edge_mma, cudaFuncAttributeMaxDynamicSharedMemorySize,
                         EDGE_SMEM);
    cudaFuncSetAttribute(k_attn2, cudaFuncAttributeMaxDynamicSharedMemorySize,
                         65536);

    k_transpose<<<128, 256>>>(W_w, Wod_w);
    k_node<<<dim3(32, BB), 256>>>(node_fea, W_b, Wod_b, a1_w, a2_w);
    k_edge_mma<<<152, 256, EDGE_SMEM>>>(edge_fea, adj, ae_w, ae_b, We_w, We_b,
                                        edge_out);
    k_attn2<<<dim3(8, HH, BB), 256, 65536>>>(node_out);
}

// round 5
// speedup vs baseline: 3.5681x; 1.3889x over previous
#include <cuda_runtime.h>
#include <cuda_fp16.h>
#include <cstdint>

#define BB 4
#define NN 256
#define HH 8

// ---------------- scratch ----------------
__device__ float g_WT[256 * 256];
__device__ float g_WodT[256 * 256];
__device__ float g_Wh[BB * NN * 256];
__device__ float g_od[BB * NN * 256];
__device__ float g_Whi[BB * NN * HH];
__device__ float g_Whj[BB * NN * HH];
__device__ float g_e[BB * HH * NN * NN];

__device__ __forceinline__ uint32_t smem_u32(const void* p) {
    uint32_t a;
    asm("{ .reg .u64 t; cvta.to.shared.u64 t, %1; cvt.u32.u64 %0, t; }"
        : "=r"(a) : "l"(p));
    return a;
}
__device__ __forceinline__ uint32_t pkh2(float lo, float hi) {
    __half2 h = __floats2half2_rn(lo, hi);
    return *reinterpret_cast<uint32_t*>(&h);
}
__device__ __forceinline__ void mma16(float* c, uint32_t a0, uint32_t a1,
                                      uint32_t a2, uint32_t a3,
                                      uint32_t b0, uint32_t b1) {
    asm volatile(
        "mma.sync.aligned.m16n8k16.row.col.f32.f16.f16.f32 "
        "{%0,%1,%2,%3},{%4,%5,%6,%7},{%8,%9},{%0,%1,%2,%3};"
        : "+f"(c[0]), "+f"(c[1]), "+f"(c[2]), "+f"(c[3])
        : "r"(a0), "r"(a1), "r"(a2), "r"(a3), "r"(b0), "r"(b1));
}
#define CP_ASYNC16(dst, src) \
    asm volatile("cp.async.cg.shared.global [%0], [%1], 16;" \
                 :: "r"(dst), "l"(src))
#define CP_COMMIT() asm volatile("cp.async.commit_group;" ::: "memory")
#define CP_WAIT0() asm volatile("cp.async.wait_group 0;" ::: "memory")

// ---------------- K0: transpose weights for k_node ----------------
__global__ __launch_bounds__(256) void k_transpose(
    const float* __restrict__ W_w, const float* __restrict__ Wod_w)
{
    int i = blockIdx.x * blockDim.x + threadIdx.x;
    int stride = gridDim.x * blockDim.x;
    for (int idx = i; idx < 65536; idx += stride) {
        int c = idx >> 8, t = idx & 255;
        g_WT[idx] = W_w[t * 256 + c];
        g_WodT[idx] = Wod_w[t * 256 + c];
    }
}

// ---------------- K1: Wh, od, Whi, Whj ----------------
__global__ __launch_bounds__(256) void k_node(
    const float* __restrict__ node_fea,
    const float* __restrict__ W_b, const float* __restrict__ Wod_b,
    const float* __restrict__ a1_w, const float* __restrict__ a2_w)
{
    __shared__ float nf_s[8][256];
    __shared__ float wh_s[8][256];
    int t = threadIdx.x;
    int b = blockIdx.y;
    int i0 = blockIdx.x * 8;

    for (int x = t; x < 8 * 256; x += 256) {
        int r = x >> 8, c = x & 255;
        int h = c >> 5, d = c & 31;
        nf_s[r][c] = node_fea[((b * HH + h) * NN + (i0 + r)) * 32 + d];
    }
    __syncthreads();

    float wh[8], odv[8];
    float wb = W_b[t], wob = Wod_b[t];
#pragma unroll
    for (int r = 0; r < 8; ++r) { wh[r] = wb; odv[r] = wob; }

#pragma unroll 4
    for (int c = 0; c < 256; ++c) {
        float wt = g_WT[c * 256 + t];
        float wo = g_WodT[c * 256 + t];
#pragma unroll
        for (int r = 0; r < 8; ++r) {
            float nv = nf_s[r][c];
            wh[r] = fmaf(nv, wt, wh[r]);
            odv[r] = fmaf(nv, wo, odv[r]);
        }
    }
#pragma unroll
    for (int r = 0; r < 8; ++r) {
        int row = b * NN + i0 + r;
        g_Wh[row * 256 + t] = wh[r];
        g_od[row * 256 + t] = odv[r];
        wh_s[r][t] = wh[r];
    }
    __syncthreads();

    int wid = t >> 5, lane = t & 31;
#pragma unroll 1
    for (int r = 0; r < 8; ++r) {
        float s1 = 0.f, s2 = 0.f;
#pragma unroll
        for (int k = 0; k < 8; ++k) {
            int c = lane + k * 32;
            float wv = wh_s[r][c];
            s1 = fmaf(wv, a1_w[wid * 256 + c], s1);
            s2 = fmaf(wv, a2_w[wid * 256 + c], s2);
        }
#pragma unroll
        for (int off = 16; off; off >>= 1) {
            s1 += __shfl_down_sync(0xffffffffu, s1, off);
            s2 += __shfl_down_sync(0xffffffffu, s2, off);
        }
        if (lane == 0) {
            int row = b * NN + i0 + r;
            g_Whi[row * 8 + wid] = s1;
            g_Whj[row * 8 + wid] = s2;
        }
    }
}

// ---------------- K2: fp16 mma.sync edge kernel, 64-row tiles, 2 CTA/SM ----------------
// smem floats: s_oib[2][256] | sA[64][136] fp32 | sB 8448 uint2 (fp16 frags)
#define SOFF_A 512
#define SOFF_B (512 + 64 * 136)
#define EDGE_SMEM_FLOATS (512 + 64 * 136 + 8448 * 2)
#define EDGE_SMEM (EDGE_SMEM_FLOATS * 4)
#define NTILES 4096
#define EGRID 296

__global__ __launch_bounds__(256, 2) void k_edge_mma(
    const float* __restrict__ edge_fea, const int* __restrict__ adj,
    const float* __restrict__ ae_w, const float* __restrict__ ae_b,
    const float* __restrict__ We_w, const float* __restrict__ We_b,
    float* __restrict__ edge_out)
{
    extern __shared__ float sf[];
    float* s_oib = sf;
    float* sA = sf + SOFF_A;                 // [64][136] fp32
    uint2* sB = reinterpret_cast<uint2*>(sf + SOFF_B);
    uint32_t sA_u = smem_u32(sA);

    int t = threadIdx.x;
    int w = t >> 5, lane = t & 31;
    int mg = w >> 2, ng = w & 3;             // mg: 2 groups of 32 rows
    int lr = lane >> 2, lc = lane & 3;

    // tile u -> b = u>>10, i = (u>>2)&255, j0 = (u&3)<<6
    auto issue_A = [&](int u) {
        int b = u >> 10, i = (u >> 2) & 255, j0 = (u & 3) << 6;
#pragma unroll
        for (int cch = 0; cch < 8; ++cch) {
            int g = (cch << 8) + t;          // 2048 chunks
            int j = g >> 5, r = g & 31, h = r >> 2, dq = r & 3;
            const float* src =
                edge_fea + ((((b * 8 + h) * NN + i) * NN) + j0 + j) * 16 + dq * 4;
            uint32_t dst = sA_u + (uint32_t)(j * 544 + h * 64 + dq * 16);
            CP_ASYNC16(dst, src);
        }
    };
    auto load_oib = [&](int u, int slot) {
        int b = u >> 10, i = (u >> 2) & 255;
        s_oib[slot * 256 + t] = g_od[(b * NN + i) * 256 + t] + We_b[t];
    };

    int u = blockIdx.x;
    issue_A(u);
    load_oib(u, 0);
    CP_COMMIT();

    // ---- pack B (once): fp16 frags. nt<32: We rows; nt==32: ae (logit columns)
    for (int x = t; x < 8448; x += 256) {
        int ln = x & 31;
        int nt = (x >> 5) % 33;
        int s = x / (33 * 32);
        int plr = ln >> 2, plc = ln & 3;
        int k0 = s * 16 + plc * 2;
        const float* src = (nt < 32) ? (We_w + (nt * 8 + plr) * 128)
                                     : (ae_w + plr * 128);
        uint2 pk;
        pk.x = pkh2(src[k0], src[k0 + 1]);
        pk.y = pkh2(src[k0 + 8], src[k0 + 9]);
        sB[(s * 33 + nt) * 32 + ln] = pk;
    }

    int buf = 0;
    while (u < NTILES) {
        CP_WAIT0();
        __syncthreads();
        int b = u >> 10, i = (u >> 2) & 255, j0 = (u & 3) << 6;

        float c[2][8][4];
        float c8[2][4];
#pragma unroll
        for (int a = 0; a < 2; ++a) {
#pragma unroll
            for (int n = 0; n < 8; ++n)
#pragma unroll
                for (int q = 0; q < 4; ++q) c[a][n][q] = 0.f;
#pragma unroll
            for (int q = 0; q < 4; ++q) c8[a][q] = 0.f;
        }

        const float2* sA2 = reinterpret_cast<const float2*>(sA);
#pragma unroll
        for (int s = 0; s < 8; ++s) {
            int cb = s * 8 + lc;             // float2 col within row
            uint32_t A[2][4];
#pragma unroll
            for (int m = 0; m < 2; ++m) {
                int r0 = (mg * 32 + m * 16 + lr) * 68 + cb;
                float2 f0 = sA2[r0];
                float2 f1 = sA2[r0 + 8 * 68];
                float2 f2 = sA2[r0 + 4];
                float2 f3 = sA2[r0 + 8 * 68 + 4];
                A[m][0] = pkh2(f0.x, f0.y);
                A[m][1] = pkh2(f1.x, f1.y);
                A[m][2] = pkh2(f2.x, f2.y);
                A[m][3] = pkh2(f3.x, f3.y);
            }
            uint2 Bv[8];
#pragma unroll
            for (int n = 0; n < 8; ++n)
                Bv[n] = sB[(s * 33 + ng * 8 + n) * 32 + lane];
#pragma unroll
            for (int m = 0; m < 2; ++m)
#pragma unroll
                for (int n = 0; n < 8; ++n)
                    mma16(c[m][n], A[m][0], A[m][1], A[m][2], A[m][3],
                          Bv[n].x, Bv[n].y);
            if (ng == 0) {
                uint2 B8 = sB[(s * 33 + 32) * 32 + lane];
#pragma unroll
                for (int m = 0; m < 2; ++m)
                    mma16(c8[m], A[m][0], A[m][1], A[m][2], A[m][3],
                          B8.x, B8.y);
            }
        }
        __syncthreads();

        // ---- prefetch next tile's A while epilogue runs
        int un = u + EGRID;
        if (un < NTILES) {
            issue_A(un);
            load_oib(un, buf ^ 1);
        }
        CP_COMMIT();

        // ---- logits epilogue (ng==0 warps cover all 64 rows via mg)
        if (ng == 0) {
            int hp = lc * 2;
            float2 whi = *reinterpret_cast<const float2*>(
                g_Whi + (b * NN + i) * 8 + hp);
            float2 aeb = *reinterpret_cast<const float2*>(ae_b + hp);
            float bi0 = whi.x + aeb.x, bi1 = whi.y + aeb.y;
            const int* adjrow = adj + (b * NN + i) * NN;
#pragma unroll
            for (int m = 0; m < 2; ++m) {
                int jg = j0 + mg * 32 + m * 16 + lr;
#pragma unroll
                for (int half = 0; half < 2; ++half) {
                    int row = jg + half * 8;
                    float2 whj = *reinterpret_cast<const float2*>(
                        g_Whj + (b * NN + row) * 8 + hp);
                    int av = adjrow[row];
                    float e0 = c8[m][half * 2] + bi0 + whj.x;
                    float e1 = c8[m][half * 2 + 1] + bi1 + whj.y;
                    e0 = (e0 > 0.f) ? e0 : 0.2f * e0;
                    e1 = (e1 > 0.f) ? e1 : 0.2f * e1;
                    if (av <= 0) { e0 = -9e15f; e1 = -9e15f; }
                    g_e[((b * 8 + hp) * NN + i) * NN + row] = e0;
                    g_e[((b * 8 + hp + 1) * NN + i) * NN + row] = e1;
                }
            }
        }

        // ---- edge stores
        const float* oib = s_oib + buf * 256;
#pragma unroll
        for (int n = 0; n < 8; ++n) {
            int n0 = ng * 64 + n * 8;
            int h = n0 >> 5;
            int dd = (n0 & 31) + lc * 2;
            float2 ob = *reinterpret_cast<const float2*>(oib + n0 + lc * 2);
            int base = ((b * 8 + h) * NN + i) * NN;
#pragma unroll
            for (int m = 0; m < 2; ++m) {
                int jg = j0 + mg * 32 + m * 16 + lr;
                float2 od0 = *reinterpret_cast<const float2*>(
                    g_od + (b * NN + jg) * 256 + n0 + lc * 2);
                float2 od1 = *reinterpret_cast<const float2*>(
                    g_od + (b * NN + jg + 8) * 256 + n0 + lc * 2);
                float2 o0, o1;
                o0.x = c[m][n][0] + ob.x + od0.x;
                o0.y = c[m][n][1] + ob.y + od0.y;
                o1.x = c[m][n][2] + ob.x + od1.x;
                o1.y = c[m][n][3] + ob.y + od1.y;
                *reinterpret_cast<float2*>(edge_out + (base + jg) * 32 + dd) = o0;
                *reinterpret_cast<float2*>(edge_out + (base + jg + 8) * 32 + dd) = o1;
            }
        }
        u = un;
        buf ^= 1;
    }
}

// ---------------- K3: softmax + node_new (warp-autonomous) ----------------
__global__ __launch_bounds__(256) void k_attn2(float* __restrict__ node_out)
{
    extern __shared__ float sm2[];
    float* Whs = sm2;           // [256][32]
    float* att = sm2 + 8192;    // [32][256]
    int t = threadIdx.x, w = t >> 5, lane = t & 31;
    int i0 = blockIdx.x << 5, h = blockIdx.y, b = blockIdx.z;

    float4* Wh4 = reinterpret_cast<float4*>(Whs);
    const float4* g4 = reinterpret_cast<const float4*>(g_Wh);
    for (int x = t; x < 2048; x += 256) {
        int j = x >> 3, dq = x & 7;
        Wh4[x] = g4[(b * NN + j) * 64 + (h << 3) + dq];
    }
    __syncthreads();

    const float4* e4 = reinterpret_cast<const float4*>(g_e);
#pragma unroll
    for (int r = 0; r < 4; ++r) {
        int il = w + (r << 3);
        int i = i0 + il;
        int idx = (((b << 3) + h) * NN + i) * 64 + (lane << 1);
        float4 x0 = e4[idx], x1 = e4[idx + 1];
        float mx = fmaxf(fmaxf(fmaxf(x0.x, x0.y), fmaxf(x0.z, x0.w)),
                         fmaxf(fmaxf(x1.x, x1.y), fmaxf(x1.z, x1.w)));
#pragma unroll
        for (int o = 16; o; o >>= 1)
            mx = fmaxf(mx, __shfl_xor_sync(0xffffffffu, mx, o));
        float p0 = __expf(x0.x - mx), p1 = __expf(x0.y - mx);
        float p2 = __expf(x0.z - mx), p3 = __expf(x0.w - mx);
        float p4 = __expf(x1.x - mx), p5 = __expf(x1.y - mx);
        float p6 = __expf(x1.z - mx), p7 = __expf(x1.w - mx);
        float s = ((p0 + p1) + (p2 + p3)) + ((p4 + p5) + (p6 + p7));
#pragma unroll
        for (int o = 16; o; o >>= 1)
            s += __shfl_xor_sync(0xffffffffu, s, o);
        float rinv = 1.0f / s;
        float4 y0 = {p0 * rinv, p1 * rinv, p2 * rinv, p3 * rinv};
        float4 y1 = {p4 * rinv, p5 * rinv, p6 * rinv, p7 * rinv};
        float4* arow = reinterpret_cast<float4*>(att + il * 256);
        arow[lane * 2] = y0;
        arow[lane * 2 + 1] = y1;
    }
    __syncwarp();

    float acc0 = 0.f, acc1 = 0.f, acc2 = 0.f, acc3 = 0.f;
    const float4* a0 = reinterpret_cast<const float4*>(att + w * 256);
    const float4* a1 = reinterpret_cast<const float4*>(att + (w + 8) * 256);
    const float4* a2 = reinterpret_cast<const float4*>(att + (w + 16) * 256);
    const float4* a3 = reinterpret_cast<const float4*>(att + (w + 24) * 256);
#pragma unroll 4
    for (int jq = 0; jq < 64; ++jq) {
        int j = jq << 2;
        float w0 = Whs[j * 32 + lane];
        float w1 = Whs[(j + 1) * 32 + lane];
        float w2 = Whs[(j + 2) * 32 + lane];
        float w3 = Whs[(j + 3) * 32 + lane];
        float4 q;
        q = a0[jq]; acc0 += q.x * w0 + q.y * w1 + q.z * w2 + q.w * w3;
        q = a1[jq]; acc1 += q.x * w0 + q.y * w1 + q.z * w2 + q.w * w3;
        q = a2[jq]; acc2 += q.x * w0 + q.y * w1 + q.z * w2 + q.w * w3;
        q = a3[jq]; acc3 += q.x * w0 + q.y * w1 + q.z * w2 + q.w * w3;
    }
    float accs[4] = {acc0, acc1, acc2, acc3};
#pragma unroll
    for (int r = 0; r < 4; ++r) {
        int i = i0 + w + (r << 3);
        node_out[(((b << 3) + h) * NN + i) * 32 + lane] =
            accs[r] + Whs[i * 32 + lane];
    }
}

// ---------------- launch ----------------
extern "C" void kernel_launch(void* const* d_in, const int* in_sizes, int n_in,
                              void* d_out, int out_size)
{
    const float* node_fea = (const float*)d_in[0];
    const float* edge_fea = (const float*)d_in[1];
    const int* adj = (const int*)d_in[2];
    const float* W_w = (const float*)d_in[3];
    const float* W_b = (const float*)d_in[4];
    const float* a1_w = (const float*)d_in[5];
    const float* a2_w = (const float*)d_in[6];
    const float* ae_w = (const float*)d_in[7];
    const float* ae_b = (const float*)d_in[8];
    const float* We_w = (const float*)d_in[9];
    const float* We_b = (const float*)d_in[10];
    const float* Wod_w = (const float*)d_in[11];
    const float* Wod_b = (const float*)d_in[12];

    float* out = (float*)d_out;
    float* node_out = out;                       // [B,H,N,DNO]
    float* edge_out = out + BB * HH * NN * 32;   // [B,H,N,N,DEO]

    cudaFuncSetAttribute(k_edge_mma, cudaFuncAttributeMaxDynamicSharedMemorySize,
                         EDGE_SMEM);
    cudaFuncSetAttribute(k_attn2, cudaFuncAttributeMaxDynamicSharedMemorySize,
                         65536);

    k_transpose<<<128, 256>>>(W_w, Wod_w);
    k_node<<<dim3(32, BB), 256>>>(node_fea, W_b, Wod_b, a1_w, a2_w);
    k_edge_mma<<<EGRID, 256, EDGE_SMEM>>>(edge_fea, adj, ae_w, ae_b, We_w, We_b,
                                          edge_out);
    k_attn2<<<dim3(8, HH, BB), 256, 65536>>>(node_out);
}

// round 6
// speedup vs baseline: 4.0497x; 1.1350x over previous
#include <cuda_runtime.h>
#include <cuda_fp16.h>
#include <cstdint>

#define BB 4
#define NN 256
#define HH 8

// ---------------- scratch ----------------
__device__ float g_WT[256 * 256];
__device__ float g_WodT[256 * 256];
__device__ float g_Wh[BB * NN * 256];
__device__ float g_od[BB * NN * 256];
__device__ float g_Whi[BB * NN * HH];
__device__ float g_Whj[BB * NN * HH];
__device__ float g_e[BB * HH * NN * NN];   // holds exp(leaky(logit)) (masked -> 0)

__device__ __forceinline__ uint32_t smem_u32(const void* p) {
    uint32_t a;
    asm("{ .reg .u64 t; cvta.to.shared.u64 t, %1; cvt.u32.u64 %0, t; }"
        : "=r"(a) : "l"(p));
    return a;
}
__device__ __forceinline__ uint32_t pkh2(float lo, float hi) {
    __half2 h = __floats2half2_rn(lo, hi);
    return *reinterpret_cast<uint32_t*>(&h);
}
__device__ __forceinline__ void mma16(float* c, uint32_t a0, uint32_t a1,
                                      uint32_t a2, uint32_t a3,
                                      uint32_t b0, uint32_t b1) {
    asm volatile(
        "mma.sync.aligned.m16n8k16.row.col.f32.f16.f16.f32 "
        "{%0,%1,%2,%3},{%4,%5,%6,%7},{%8,%9},{%0,%1,%2,%3};"
        : "+f"(c[0]), "+f"(c[1]), "+f"(c[2]), "+f"(c[3])
        : "r"(a0), "r"(a1), "r"(a2), "r"(a3), "r"(b0), "r"(b1));
}
#define LDSM4(r0, r1, r2, r3, addr) \
    asm volatile("ldmatrix.sync.aligned.m8n8.x4.shared.b16 {%0,%1,%2,%3},[%4];" \
                 : "=r"(r0), "=r"(r1), "=r"(r2), "=r"(r3) : "r"(addr))

// ---------------- K0: transpose weights for k_node ----------------
__global__ __launch_bounds__(256) void k_transpose(
    const float* __restrict__ W_w, const float* __restrict__ Wod_w)
{
    int i = blockIdx.x * blockDim.x + threadIdx.x;
    int stride = gridDim.x * blockDim.x;
    for (int idx = i; idx < 65536; idx += stride) {
        int c = idx >> 8, t = idx & 255;
        g_WT[idx] = W_w[t * 256 + c];
        g_WodT[idx] = Wod_w[t * 256 + c];
    }
}

// ---------------- K1: Wh, od, Whi, Whj ----------------
__global__ __launch_bounds__(256) void k_node(
    const float* __restrict__ node_fea,
    const float* __restrict__ W_b, const float* __restrict__ Wod_b,
    const float* __restrict__ a1_w, const float* __restrict__ a2_w)
{
    __shared__ float nf_s[8][256];
    __shared__ float wh_s[8][256];
    int t = threadIdx.x;
    int b = blockIdx.y;
    int i0 = blockIdx.x * 8;

    for (int x = t; x < 8 * 256; x += 256) {
        int r = x >> 8, c = x & 255;
        int h = c >> 5, d = c & 31;
        nf_s[r][c] = node_fea[((b * HH + h) * NN + (i0 + r)) * 32 + d];
    }
    __syncthreads();

    float wh[8], odv[8];
    float wb = W_b[t], wob = Wod_b[t];
#pragma unroll
    for (int r = 0; r < 8; ++r) { wh[r] = wb; odv[r] = wob; }

#pragma unroll 4
    for (int c = 0; c < 256; ++c) {
        float wt = g_WT[c * 256 + t];
        float wo = g_WodT[c * 256 + t];
#pragma unroll
        for (int r = 0; r < 8; ++r) {
            float nv = nf_s[r][c];
            wh[r] = fmaf(nv, wt, wh[r]);
            odv[r] = fmaf(nv, wo, odv[r]);
        }
    }
#pragma unroll
    for (int r = 0; r < 8; ++r) {
        int row = b * NN + i0 + r;
        g_Wh[row * 256 + t] = wh[r];
        g_od[row * 256 + t] = odv[r];
        wh_s[r][t] = wh[r];
    }
    __syncthreads();

    int wid = t >> 5, lane = t & 31;
#pragma unroll 1
    for (int r = 0; r < 8; ++r) {
        float s1 = 0.f, s2 = 0.f;
#pragma unroll
        for (int k = 0; k < 8; ++k) {
            int c = lane + k * 32;
            float wv = wh_s[r][c];
            s1 = fmaf(wv, a1_w[wid * 256 + c], s1);
            s2 = fmaf(wv, a2_w[wid * 256 + c], s2);
        }
#pragma unroll
        for (int off = 16; off; off >>= 1) {
            s1 += __shfl_down_sync(0xffffffffu, s1, off);
            s2 += __shfl_down_sync(0xffffffffu, s2, off);
        }
        if (lane == 0) {
            int row = b * NN + i0 + r;
            g_Whi[row * 8 + wid] = s1;
            g_Whj[row * 8 + wid] = s2;
        }
    }
}

// ---------------- K2: fp16 mma edge kernel, ldmatrix A, permuted B, f4 stores ----
// smem bytes: sB4 uint4[4096] @0 (64KB) | sB8 uint2[256] @65536 (2KB) |
//             sA16 half[64*136] @67584 (17KB) | s_oib float[2][256] @84992 (2KB)
#define OFF_B4 0
#define OFF_B8 65536
#define OFF_A16 67584
#define OFF_OIB 84992
#define EDGE_SMEM 87040
#define NTILES 4096
#define EGRID 296

__global__ __launch_bounds__(256, 2) void k_edge_mma(
    const float* __restrict__ edge_fea, const int* __restrict__ adj,
    const float* __restrict__ ae_w, const float* __restrict__ ae_b,
    const float* __restrict__ We_w, const float* __restrict__ We_b,
    float* __restrict__ edge_out)
{
    extern __shared__ char smc[];
    uint4* sB4 = reinterpret_cast<uint4*>(smc + OFF_B4);
    uint2* sB8 = reinterpret_cast<uint2*>(smc + OFF_B8);
    char* sA16 = smc + OFF_A16;
    float* s_oib = reinterpret_cast<float*>(smc + OFF_OIB);
    uint32_t sA_u = smem_u32(sA16);

    int t = threadIdx.x;
    int w = t >> 5, lane = t & 31;
    int mg = w >> 2, ng = w & 3;
    int lr = lane >> 2, lc = lane & 3;

    // ldmatrix per-lane base: row = lane&15 within 16-row group, khalf = lane>>4
    uint32_t lds_base = sA_u + (uint32_t)((mg * 32 + (lane & 15)) * 272 +
                                          (lane >> 4) * 16);

    // ---- B pack (permuted pairs) ----
    // pair np covers 16 cols; frag f, B-row rn -> actual n = np*16 + 4*(rn>>1)+2f+(rn&1)
    for (int x = t; x < 4096; x += 256) {
        int s = x >> 9, np = (x >> 5) & 15, l = x & 31;
        int rn = l >> 2, plc = l & 3;
        int n0 = np * 16 + ((rn >> 1) << 2) + (rn & 1);
        int k0 = s * 16 + plc * 2;
        const float* w0 = We_w + n0 * 128 + k0;
        const float* w1 = We_w + (n0 + 2) * 128 + k0;
        uint4 pk;
        pk.x = pkh2(w0[0], w0[1]);
        pk.y = pkh2(w0[8], w0[9]);
        pk.z = pkh2(w1[0], w1[1]);
        pk.w = pkh2(w1[8], w1[9]);
        sB4[x] = pk;
    }
    {   // logit columns (ae) as classic uint2 frags
        int x = t;
        if (x < 256) {
            int s = x >> 5, l = x & 31;
            int rn = l >> 2, plc = l & 3;
            const float* src = ae_w + rn * 128 + s * 16 + plc * 2;
            uint2 pk;
            pk.x = pkh2(src[0], src[1]);
            pk.y = pkh2(src[8], src[9]);
            sB8[x] = pk;
        }
    }

    // ---- A load helpers: tile u -> b=u>>10, i=(u>>2)&255, j0=(u&3)<<6
    float4 Areg[8];
    auto load_A = [&](int u) {
        int b = u >> 10, i = (u >> 2) & 255, j0 = (u & 3) << 6;
#pragma unroll
        for (int it = 0; it < 8; ++it) {
            int idx = it * 256 + t;
            int h = idx >> 8, r = idx & 255, j = r >> 2, dq = r & 3;
            Areg[it] = *reinterpret_cast<const float4*>(
                edge_fea + ((((b * 8 + h) * NN + i) * NN) + j0 + j) * 16 + dq * 4);
        }
    };
    auto store_A = [&]() {
#pragma unroll
        for (int it = 0; it < 8; ++it) {
            int idx = it * 256 + t;
            int h = idx >> 8, r = idx & 255, j = r >> 2, dq = r & 3;
            uint2 pk;
            pk.x = pkh2(Areg[it].x, Areg[it].y);
            pk.y = pkh2(Areg[it].z, Areg[it].w);
            *reinterpret_cast<uint2*>(sA16 + j * 272 + h * 32 + dq * 8) = pk;
        }
    };
    auto load_oib = [&](int u, int slot) {
        int b = u >> 10, i = (u >> 2) & 255;
        s_oib[slot * 256 + t] = g_od[(b * NN + i) * 256 + t] + We_b[t];
    };

    int u = blockIdx.x;
    load_A(u);
    store_A();
    load_oib(u, 0);
    __syncthreads();

    int buf = 0;
    while (u < NTILES) {
        int b = u >> 10, i = (u >> 2) & 255, j0 = (u & 3) << 6;

        float c[2][8][4];
        float c8[2][4];
#pragma unroll
        for (int a = 0; a < 2; ++a) {
#pragma unroll
            for (int n = 0; n < 8; ++n)
#pragma unroll
                for (int q = 0; q < 4; ++q) c[a][n][q] = 0.f;
#pragma unroll
            for (int q = 0; q < 4; ++q) c8[a][q] = 0.f;
        }

        // ---- mainloop
#pragma unroll
        for (int s = 0; s < 8; ++s) {
            uint32_t A[2][4];
#pragma unroll
            for (int m = 0; m < 2; ++m)
                LDSM4(A[m][0], A[m][1], A[m][2], A[m][3],
                      lds_base + (uint32_t)(m * 4352 + s * 32));
            uint4 Bv[4];
#pragma unroll
            for (int p = 0; p < 4; ++p)
                Bv[p] = sB4[(s * 16 + ng * 4 + p) * 32 + lane];
#pragma unroll
            for (int m = 0; m < 2; ++m)
#pragma unroll
                for (int p = 0; p < 4; ++p) {
                    mma16(c[m][2 * p], A[m][0], A[m][1], A[m][2], A[m][3],
                          Bv[p].x, Bv[p].y);
                    mma16(c[m][2 * p + 1], A[m][0], A[m][1], A[m][2], A[m][3],
                          Bv[p].z, Bv[p].w);
                }
            if (ng == 0) {
                uint2 B8 = sB8[s * 32 + lane];
#pragma unroll
                for (int m = 0; m < 2; ++m)
                    mma16(c8[m], A[m][0], A[m][1], A[m][2], A[m][3],
                          B8.x, B8.y);
            }
        }
        __syncthreads();   // A consumed; safe to refill sA16 later

        int un = u + EGRID;
        if (un < NTILES) load_A(un);   // LDG in flight over epilogue

        // ---- logits epilogue: store exp(leaky(e)), masked -> 0
        if (ng == 0) {
            int hp = lc * 2;
            float2 whi = *reinterpret_cast<const float2*>(
                g_Whi + (b * NN + i) * 8 + hp);
            float2 aeb = *reinterpret_cast<const float2*>(ae_b + hp);
            float bi0 = whi.x + aeb.x, bi1 = whi.y + aeb.y;
            const int* adjrow = adj + (b * NN + i) * NN;
#pragma unroll
            for (int m = 0; m < 2; ++m) {
                int jg = j0 + mg * 32 + m * 16 + lr;
#pragma unroll
                for (int half = 0; half < 2; ++half) {
                    int row = jg + half * 8;
                    float2 whj = *reinterpret_cast<const float2*>(
                        g_Whj + (b * NN + row) * 8 + hp);
                    int av = adjrow[row];
                    float e0 = c8[m][half * 2] + bi0 + whj.x;
                    float e1 = c8[m][half * 2 + 1] + bi1 + whj.y;
                    e0 = (e0 > 0.f) ? e0 : 0.2f * e0;
                    e1 = (e1 > 0.f) ? e1 : 0.2f * e1;
                    float p0 = (av <= 0) ? 0.f : __expf(e0);
                    float p1 = (av <= 0) ? 0.f : __expf(e1);
                    g_e[((b * 8 + hp) * NN + i) * NN + row] = p0;
                    g_e[((b * 8 + hp + 1) * NN + i) * NN + row] = p1;
                }
            }
        }

        // ---- edge stores: float4 per thread (permuted C cols are consecutive)
        const float* oib = s_oib + buf * 256;
#pragma unroll
        for (int p = 0; p < 4; ++p) {
            int np = ng * 4 + p;
            int h = np >> 1;
            int nb = (np << 4) + (lc << 2);          // n base (0..255)
            int dd = nb & 31;
            float4 ob = *reinterpret_cast<const float4*>(oib + nb);
            int rowbase = ((b * 8 + h) * NN + i) * NN;
#pragma unroll
            for (int m = 0; m < 2; ++m) {
#pragma unroll
                for (int h2 = 0; h2 < 2; ++h2) {
                    int j = j0 + mg * 32 + m * 16 + lr + h2 * 8;
                    float4 od = *reinterpret_cast<const float4*>(
                        g_od + (b * NN + j) * 256 + nb);
                    float4 o;
                    o.x = c[m][2 * p][h2 * 2 + 0] + ob.x + od.x;
                    o.y = c[m][2 * p][h2 * 2 + 1] + ob.y + od.y;
                    o.z = c[m][2 * p + 1][h2 * 2 + 0] + ob.z + od.z;
                    o.w = c[m][2 * p + 1][h2 * 2 + 1] + ob.w + od.w;
                    *reinterpret_cast<float4*>(
                        edge_out + (size_t)(rowbase + j) * 32 + dd) = o;
                }
            }
        }

        if (un < NTILES) {
            store_A();
            load_oib(un, buf ^ 1);
        }
        __syncthreads();
        u = un;
        buf ^= 1;
    }
}

// ---------------- K3: normalize pre-exp'd scores + node_new ----------------
__global__ __launch_bounds__(256) void k_attn3(float* __restrict__ node_out)
{
    extern __shared__ float sm2[];
    float* Whs = sm2;           // [256][32]
    float* att = sm2 + 8192;    // [32][256]
    int t = threadIdx.x, w = t >> 5, lane = t & 31;
    int i0 = blockIdx.x << 5, h = blockIdx.y, b = blockIdx.z;

    float4* Wh4 = reinterpret_cast<float4*>(Whs);
    const float4* g4 = reinterpret_cast<const float4*>(g_Wh);
    for (int x = t; x < 2048; x += 256) {
        int j = x >> 3, dq = x & 7;
        Wh4[x] = g4[(b * NN + j) * 64 + (h << 3) + dq];
    }
    __syncthreads();

    const float4* e4 = reinterpret_cast<const float4*>(g_e);
#pragma unroll
    for (int r = 0; r < 4; ++r) {
        int il = w + (r << 3);
        int i = i0 + il;
        int idx = (((b << 3) + h) * NN + i) * 64 + (lane << 1);
        float4 x0 = e4[idx], x1 = e4[idx + 1];
        float s = ((x0.x + x0.y) + (x0.z + x0.w)) +
                  ((x1.x + x1.y) + (x1.z + x1.w));
#pragma unroll
        for (int o = 16; o; o >>= 1)
            s += __shfl_xor_sync(0xffffffffu, s, o);
        float rinv = 1.0f / s;
        float4 y0 = {x0.x * rinv, x0.y * rinv, x0.z * rinv, x0.w * rinv};
        float4 y1 = {x1.x * rinv, x1.y * rinv, x1.z * rinv, x1.w * rinv};
        float4* arow = reinterpret_cast<float4*>(att + il * 256);
        arow[lane * 2] = y0;
        arow[lane * 2 + 1] = y1;
    }
    __syncwarp();

    float acc0 = 0.f, acc1 = 0.f, acc2 = 0.f, acc3 = 0.f;
    const float4* a0 = reinterpret_cast<const float4*>(att + w * 256);
    const float4* a1 = reinterpret_cast<const float4*>(att + (w + 8) * 256);
    const float4* a2 = reinterpret_cast<const float4*>(att + (w + 16) * 256);
    const float4* a3 = reinterpret_cast<const float4*>(att + (w + 24) * 256);
#pragma unroll 4
    for (int jq = 0; jq < 64; ++jq) {
        int j = jq << 2;
        float w0 = Whs[j * 32 + lane];
        float w1 = Whs[(j + 1) * 32 + lane];
        float w2 = Whs[(j + 2) * 32 + lane];
        float w3 = Whs[(j + 3) * 32 + lane];
        float4 q;
        q = a0[jq]; acc0 += q.x * w0 + q.y * w1 + q.z * w2 + q.w * w3;
        q = a1[jq]; acc1 += q.x * w0 + q.y * w1 + q.z * w2 + q.w * w3;
        q = a2[jq]; acc2 += q.x * w0 + q.y * w1 + q.z * w2 + q.w * w3;
        q = a3[jq]; acc3 += q.x * w0 + q.y * w1 + q.z * w2 + q.w * w3;
    }
    float accs[4] = {acc0, acc1, acc2, acc3};
#pragma unroll
    for (int r = 0; r < 4; ++r) {
        int i = i0 + w + (r << 3);
        node_out[(((b << 3) + h) * NN + i) * 32 + lane] =
            accs[r] + Whs[i * 32 + lane];
    }
}

// ---------------- launch ----------------
extern "C" void kernel_launch(void* const* d_in, const int* in_sizes, int n_in,
                              void* d_out, int out_size)
{
    const float* node_fea = (const float*)d_in[0];
    const float* edge_fea = (const float*)d_in[1];
    const int* adj = (const int*)d_in[2];
    const float* W_w = (const float*)d_in[3];
    const float* W_b = (const float*)d_in[4];
    const float* a1_w = (const float*)d_in[5];
    const float* a2_w = (const float*)d_in[6];
    const float* ae_w = (const float*)d_in[7];
    const float* ae_b = (const float*)d_in[8];
    const float* We_w = (const float*)d_in[9];
    const float* We_b = (const float*)d_in[10];
    const float* Wod_w = (const float*)d_in[11];
    const float* Wod_b = (const float*)d_in[12];

    float* out = (float*)d_out;
    float* node_out = out;                       // [B,H,N,DNO]
    float* edge_out = out + BB * HH * NN * 32;   // [B,H,N,N,DEO]

    cudaFuncSetAttribute(k_edge_mma, cudaFuncAttributeMaxDynamicSharedMemorySize,
                         EDGE_SMEM);
    cudaFuncSetAttribute(k_attn3, cudaFuncAttributeMaxDynamicSharedMemorySize,
                         65536);

    k_transpose<<<128, 256>>>(W_w, Wod_w);
    k_node<<<dim3(32, BB), 256>>>(node_fea, W_b, Wod_b, a1_w, a2_w);
    k_edge_mma<<<EGRID, 256, EDGE_SMEM>>>(edge_fea, adj, ae_w, ae_b, We_w, We_b,
                                          edge_out);
    k_attn3<<<dim3(8, HH, BB), 256, 65536>>>(node_out);
}

// round 7
// speedup vs baseline: 4.0519x; 1.0005x over previous
#include <cuda_runtime.h>
#include <cuda_fp16.h>
#include <cstdint>

#define BB 4
#define NN 256
#define HH 8

// ---------------- scratch ----------------
__device__ float g_WT[256 * 256];
__device__ float g_WodT[256 * 256];
__device__ float g_Wh[BB * NN * 256];
__device__ float g_od[BB * NN * 256];
__device__ float g_Whi[BB * NN * HH];
__device__ float g_Whj[BB * NN * HH];
__device__ float g_e[BB * HH * NN * NN];   // holds exp(leaky(logit)) (masked -> 0)

__device__ __forceinline__ uint32_t smem_u32(const void* p) {
    uint32_t a;
    asm("{ .reg .u64 t; cvta.to.shared.u64 t, %1; cvt.u32.u64 %0, t; }"
        : "=r"(a) : "l"(p));
    return a;
}
__device__ __forceinline__ uint32_t pkh2(float lo, float hi) {
    __half2 h = __floats2half2_rn(lo, hi);
    return *reinterpret_cast<uint32_t*>(&h);
}
__device__ __forceinline__ void mma16(float* c, uint32_t a0, uint32_t a1,
                                      uint32_t a2, uint32_t a3,
                                      uint32_t b0, uint32_t b1) {
    asm volatile(
        "mma.sync.aligned.m16n8k16.row.col.f32.f16.f16.f32 "
        "{%0,%1,%2,%3},{%4,%5,%6,%7},{%8,%9},{%0,%1,%2,%3};"
        : "+f"(c[0]), "+f"(c[1]), "+f"(c[2]), "+f"(c[3])
        : "r"(a0), "r"(a1), "r"(a2), "r"(a3), "r"(b0), "r"(b1));
}
#define LDSM4(r0, r1, r2, r3, addr) \
    asm volatile("ldmatrix.sync.aligned.m8n8.x4.shared.b16 {%0,%1,%2,%3},[%4];" \
                 : "=r"(r0), "=r"(r1), "=r"(r2), "=r"(r3) : "r"(addr))

// ---------------- K0: transpose weights for k_node ----------------
__global__ __launch_bounds__(256) void k_transpose(
    const float* __restrict__ W_w, const float* __restrict__ Wod_w)
{
    int i = blockIdx.x * blockDim.x + threadIdx.x;
    int stride = gridDim.x * blockDim.x;
    for (int idx = i; idx < 65536; idx += stride) {
        int c = idx >> 8, t = idx & 255;
        g_WT[idx] = W_w[t * 256 + c];
        g_WodT[idx] = Wod_w[t * 256 + c];
    }
}

// ---------------- K1: Wh, od, Whi, Whj ----------------
__global__ __launch_bounds__(256) void k_node(
    const float* __restrict__ node_fea,
    const float* __restrict__ W_b, const float* __restrict__ Wod_b,
    const float* __restrict__ a1_w, const float* __restrict__ a2_w)
{
    __shared__ float nf_s[8][256];
    __shared__ float wh_s[8][256];
    int t = threadIdx.x;
    int b = blockIdx.y;
    int i0 = blockIdx.x * 8;

    for (int x = t; x < 8 * 256; x += 256) {
        int r = x >> 8, c = x & 255;
        int h = c >> 5, d = c & 31;
        nf_s[r][c] = node_fea[((b * HH + h) * NN + (i0 + r)) * 32 + d];
    }
    __syncthreads();

    float wh[8], odv[8];
    float wb = W_b[t], wob = Wod_b[t];
#pragma unroll
    for (int r = 0; r < 8; ++r) { wh[r] = wb; odv[r] = wob; }

#pragma unroll 4
    for (int c = 0; c < 256; ++c) {
        float wt = g_WT[c * 256 + t];
        float wo = g_WodT[c * 256 + t];
#pragma unroll
        for (int r = 0; r < 8; ++r) {
            float nv = nf_s[r][c];
            wh[r] = fmaf(nv, wt, wh[r]);
            odv[r] = fmaf(nv, wo, odv[r]);
        }
    }
#pragma unroll
    for (int r = 0; r < 8; ++r) {
        int row = b * NN + i0 + r;
        g_Wh[row * 256 + t] = wh[r];
        g_od[row * 256 + t] = odv[r];
        wh_s[r][t] = wh[r];
    }
    __syncthreads();

    int wid = t >> 5, lane = t & 31;
#pragma unroll 1
    for (int r = 0; r < 8; ++r) {
        float s1 = 0.f, s2 = 0.f;
#pragma unroll
        for (int k = 0; k < 8; ++k) {
            int c = lane + k * 32;
            float wv = wh_s[r][c];
            s1 = fmaf(wv, a1_w[wid * 256 + c], s1);
            s2 = fmaf(wv, a2_w[wid * 256 + c], s2);
        }
#pragma unroll
        for (int off = 16; off; off >>= 1) {
            s1 += __shfl_down_sync(0xffffffffu, s1, off);
            s2 += __shfl_down_sync(0xffffffffu, s2, off);
        }
        if (lane == 0) {
            int row = b * NN + i0 + r;
            g_Whi[row * 8 + wid] = s1;
            g_Whj[row * 8 + wid] = s2;
        }
    }
}

// ---------------- K2: fp16 mma edge kernel, 64j x 128n tiles, 3 CTA/SM ----------
// smem bytes: sB4 uint4[2048] @0 (32KB) | sB8 uint2[256] @32768 (2KB) |
//             sA16 half [64*136] @34816 (17KB) | s_oib float[128] @52224
#define OFF_B4 0
#define OFF_B8 32768
#define OFF_A16 34816
#define OFF_OIB 52224
#define EDGE_SMEM 52736
#define NTILES 8192
#define EGRID 444

__global__ __launch_bounds__(256, 3) void k_edge_mma(
    const float* __restrict__ edge_fea, const int* __restrict__ adj,
    const float* __restrict__ ae_w, const float* __restrict__ ae_b,
    const float* __restrict__ We_w, const float* __restrict__ We_b,
    float* __restrict__ edge_out)
{
    extern __shared__ char smc[];
    uint4* sB4 = reinterpret_cast<uint4*>(smc + OFF_B4);
    uint2* sB8 = reinterpret_cast<uint2*>(smc + OFF_B8);
    char* sA16 = smc + OFF_A16;
    float* s_oib = reinterpret_cast<float*>(smc + OFF_OIB);
    uint32_t sA_u = smem_u32(sA16);

    int t = threadIdx.x;
    int w = t >> 5, lane = t & 31;
    int mg = w >> 2, ng = w & 3;             // mg: 2 row groups, ng: 4 n groups (32 each)
    int lr = lane >> 2, lc = lane & 3;

    int nh = blockIdx.x & 1;                 // n-half (constant: EGRID is even)

    uint32_t lds_base = sA_u + (uint32_t)((mg * 32 + (lane & 15)) * 272 +
                                          (lane >> 4) * 16);

    // ---- B pack (permuted pairs) for this n-half ----
    for (int x = t; x < 2048; x += 256) {
        int s = x >> 8, np = (x >> 5) & 7, l = x & 31;
        int rn = l >> 2, plc = l & 3;
        int n0 = nh * 128 + np * 16 + ((rn >> 1) << 2) + (rn & 1);
        int k0 = s * 16 + plc * 2;
        const float* w0 = We_w + n0 * 128 + k0;
        const float* w1 = We_w + (n0 + 2) * 128 + k0;
        uint4 pk;
        pk.x = pkh2(w0[0], w0[1]);
        pk.y = pkh2(w0[8], w0[9]);
        pk.z = pkh2(w1[0], w1[1]);
        pk.w = pkh2(w1[8], w1[9]);
        sB4[x] = pk;
    }
    if (t < 256) {   // ae logit columns as classic uint2 frags
        int s = t >> 5, l = t & 31;
        int rn = l >> 2, plc = l & 3;
        const float* src = ae_w + rn * 128 + s * 16 + plc * 2;
        uint2 pk;
        pk.x = pkh2(src[0], src[1]);
        pk.y = pkh2(src[8], src[9]);
        sB8[t] = pk;
    }

    // tile u -> b = u>>11, i = (u>>3)&255, j0 = ((u>>1)&3)<<6, nh = u&1
    for (int u = blockIdx.x; u < NTILES; u += EGRID) {
        int b = u >> 11, i = (u >> 3) & 255, j0 = ((u >> 1) & 3) << 6;

        // ---- A load: 64j x 128k fp32 -> fp16 smem (8 float4 per thread)
#pragma unroll
        for (int it = 0; it < 8; ++it) {
            int idx = it * 256 + t;
            int h = idx >> 8, r = idx & 255, j = r >> 2, dq = r & 3;
            float4 v = *reinterpret_cast<const float4*>(
                edge_fea + ((((b * 8 + h) * NN + i) * NN) + j0 + j) * 16 + dq * 4);
            uint2 pk;
            pk.x = pkh2(v.x, v.y);
            pk.y = pkh2(v.z, v.w);
            *reinterpret_cast<uint2*>(sA16 + j * 272 + h * 32 + dq * 8) = pk;
        }
        if (t < 128)
            s_oib[t] = g_od[(b * NN + i) * 256 + nh * 128 + t] +
                       We_b[nh * 128 + t];
        __syncthreads();

        // ---- mainloop
        float c[2][4][4];
        float c8[2][4];
#pragma unroll
        for (int a = 0; a < 2; ++a) {
#pragma unroll
            for (int n = 0; n < 4; ++n)
#pragma unroll
                for (int q = 0; q < 4; ++q) c[a][n][q] = 0.f;
#pragma unroll
            for (int q = 0; q < 4; ++q) c8[a][q] = 0.f;
        }

#pragma unroll
        for (int s = 0; s < 8; ++s) {
            uint32_t A[2][4];
#pragma unroll
            for (int m = 0; m < 2; ++m)
                LDSM4(A[m][0], A[m][1], A[m][2], A[m][3],
                      lds_base + (uint32_t)(m * 4352 + s * 32));
            uint4 Bv[2];
#pragma unroll
            for (int p = 0; p < 2; ++p)
                Bv[p] = sB4[(s * 8 + ng * 2 + p) * 32 + lane];
#pragma unroll
            for (int m = 0; m < 2; ++m)
#pragma unroll
                for (int p = 0; p < 2; ++p) {
                    mma16(c[m][2 * p], A[m][0], A[m][1], A[m][2], A[m][3],
                          Bv[p].x, Bv[p].y);
                    mma16(c[m][2 * p + 1], A[m][0], A[m][1], A[m][2], A[m][3],
                          Bv[p].z, Bv[p].w);
                }
            if (nh == 0 && ng == 0) {
                uint2 B8 = sB8[s * 32 + lane];
#pragma unroll
                for (int m = 0; m < 2; ++m)
                    mma16(c8[m], A[m][0], A[m][1], A[m][2], A[m][3],
                          B8.x, B8.y);
            }
        }
        __syncthreads();

        // ---- logits epilogue (nh==0, ng==0): store exp(leaky), masked -> 0
        if (nh == 0 && ng == 0) {
            int hp = lc * 2;
            float2 whi = *reinterpret_cast<const float2*>(
                g_Whi + (b * NN + i) * 8 + hp);
            float2 aeb = *reinterpret_cast<const float2*>(ae_b + hp);
            float bi0 = whi.x + aeb.x, bi1 = whi.y + aeb.y;
            const int* adjrow = adj + (b * NN + i) * NN;
#pragma unroll
            for (int m = 0; m < 2; ++m) {
                int jg = j0 + mg * 32 + m * 16 + lr;
#pragma unroll
                for (int half = 0; half < 2; ++half) {
                    int row = jg + half * 8;
                    float2 whj = *reinterpret_cast<const float2*>(
                        g_Whj + (b * NN + row) * 8 + hp);
                    int av = adjrow[row];
                    float e0 = c8[m][half * 2] + bi0 + whj.x;
                    float e1 = c8[m][half * 2 + 1] + bi1 + whj.y;
                    e0 = (e0 > 0.f) ? e0 : 0.2f * e0;
                    e1 = (e1 > 0.f) ? e1 : 0.2f * e1;
                    float p0 = (av <= 0) ? 0.f : __expf(e0);
                    float p1 = (av <= 0) ? 0.f : __expf(e1);
                    g_e[((b * 8 + hp) * NN + i) * NN + row] = p0;
                    g_e[((b * 8 + hp + 1) * NN + i) * NN + row] = p1;
                }
            }
        }

        // ---- edge stores: float4 per thread
#pragma unroll
        for (int p = 0; p < 2; ++p) {
            int npg = nh * 8 + ng * 2 + p;
            int h = npg >> 1;
            int nb = (npg << 4) + (lc << 2);         // global n base (0..255)
            int dd = nb & 31;
            float4 ob = *reinterpret_cast<const float4*>(
                s_oib + ((ng * 2 + p) << 4) + (lc << 2));
            int rowbase = ((b * 8 + h) * NN + i) * NN;
#pragma unroll
            for (int m = 0; m < 2; ++m) {
#pragma unroll
                for (int h2 = 0; h2 < 2; ++h2) {
                    int j = j0 + mg * 32 + m * 16 + lr + h2 * 8;
                    float4 od = *reinterpret_cast<const float4*>(
                        g_od + (b * NN + j) * 256 + nb);
                    float4 o;
                    o.x = c[m][2 * p][h2 * 2 + 0] + ob.x + od.x;
                    o.y = c[m][2 * p][h2 * 2 + 1] + ob.y + od.y;
                    o.z = c[m][2 * p + 1][h2 * 2 + 0] + ob.z + od.z;
                    o.w = c[m][2 * p + 1][h2 * 2 + 1] + ob.w + od.w;
                    *reinterpret_cast<float4*>(
                        edge_out + (size_t)(rowbase + j) * 32 + dd) = o;
                }
            }
        }
        __syncthreads();   // s_oib / sA16 consumed before next tile overwrites
    }
}

// ---------------- K3: normalize pre-exp'd scores + node_new ----------------
// grid (16, 8, 4); block 256; i-block = 16 rows
__global__ __launch_bounds__(256) void k_attn3(float* __restrict__ node_out)
{
    extern __shared__ float sm2[];
    float* Whs = sm2;            // [256][32] = 32KB
    float* att = sm2 + 8192;     // [16][256] = 16KB
    int t = threadIdx.x, w = t >> 5, lane = t & 31;
    int i0 = blockIdx.x << 4, h = blockIdx.y, b = blockIdx.z;

    float4* Wh4 = reinterpret_cast<float4*>(Whs);
    const float4* g4 = reinterpret_cast<const float4*>(g_Wh);
    for (int x = t; x < 2048; x += 256) {
        int j = x >> 3, dq = x & 7;
        Wh4[x] = g4[(b * NN + j) * 64 + (h << 3) + dq];
    }

    // front-load all 4 LDG.128 (rows w and w+8)
    const float4* e4 = reinterpret_cast<const float4*>(g_e);
    float4 xv[4];
#pragma unroll
    for (int r = 0; r < 2; ++r) {
        int i = i0 + w + (r << 3);
        int idx = (((b << 3) + h) * NN + i) * 64 + (lane << 1);
        xv[2 * r] = e4[idx];
        xv[2 * r + 1] = e4[idx + 1];
    }
    __syncthreads();

#pragma unroll
    for (int r = 0; r < 2; ++r) {
        int il = w + (r << 3);
        float4 x0 = xv[2 * r], x1 = xv[2 * r + 1];
        float s = ((x0.x + x0.y) + (x0.z + x0.w)) +
                  ((x1.x + x1.y) + (x1.z + x1.w));
#pragma unroll
        for (int o = 16; o; o >>= 1)
            s += __shfl_xor_sync(0xffffffffu, s, o);
        float rinv = 1.0f / s;
        float4 y0 = {x0.x * rinv, x0.y * rinv, x0.z * rinv, x0.w * rinv};
        float4 y1 = {x1.x * rinv, x1.y * rinv, x1.z * rinv, x1.w * rinv};
        float4* arow = reinterpret_cast<float4*>(att + il * 256);
        arow[lane * 2] = y0;
        arow[lane * 2 + 1] = y1;
    }
    __syncthreads();

    float acc0 = 0.f, acc1 = 0.f;
    const float4* a0 = reinterpret_cast<const float4*>(att + w * 256);
    const float4* a1 = reinterpret_cast<const float4*>(att + (w + 8) * 256);
#pragma unroll 4
    for (int jq = 0; jq < 64; ++jq) {
        int j = jq << 2;
        float w0 = Whs[j * 32 + lane];
        float w1 = Whs[(j + 1) * 32 + lane];
        float w2 = Whs[(j + 2) * 32 + lane];
        float w3 = Whs[(j + 3) * 32 + lane];
        float4 q;
        q = a0[jq]; acc0 += q.x * w0 + q.y * w1 + q.z * w2 + q.w * w3;
        q = a1[jq]; acc1 += q.x * w0 + q.y * w1 + q.z * w2 + q.w * w3;
    }
    {
        int i = i0 + w;
        node_out[(((b << 3) + h) * NN + i) * 32 + lane] =
            acc0 + Whs[i * 32 + lane];
        i = i0 + w + 8;
        node_out[(((b << 3) + h) * NN + i) * 32 + lane] =
            acc1 + Whs[i * 32 + lane];
    }
}

// ---------------- launch ----------------
extern "C" void kernel_launch(void* const* d_in, const int* in_sizes, int n_in,
                              void* d_out, int out_size)
{
    const float* node_fea = (const float*)d_in[0];
    const float* edge_fea = (const float*)d_in[1];
    const int* adj = (const int*)d_in[2];
    const float* W_w = (const float*)d_in[3];
    const float* W_b = (const float*)d_in[4];
    const float* a1_w = (const float*)d_in[5];
    const float* a2_w = (const float*)d_in[6];
    const float* ae_w = (const float*)d_in[7];
    const float* ae_b = (const float*)d_in[8];
    const float* We_w = (const float*)d_in[9];
    const float* We_b = (const float*)d_in[10];
    const float* Wod_w = (const float*)d_in[11];
    const float* Wod_b = (const float*)d_in[12];

    float* out = (float*)d_out;
    float* node_out = out;                       // [B,H,N,DNO]
    float* edge_out = out + BB * HH * NN * 32;   // [B,H,N,N,DEO]

    cudaFuncSetAttribute(k_edge_mma, cudaFuncAttributeMaxDynamicSharedMemorySize,
                         EDGE_SMEM);
    cudaFuncSetAttribute(k_attn3, cudaFuncAttributeMaxDynamicSharedMemorySize,
                         49152);

    k_transpose<<<128, 256>>>(W_w, Wod_w);
    k_node<<<dim3(32, BB), 256>>>(node_fea, W_b, Wod_b, a1_w, a2_w);
    k_edge_mma<<<EGRID, 256, EDGE_SMEM>>>(edge_fea, adj, ae_w, ae_b, We_w, We_b,
                                          edge_out);
    k_attn3<<<dim3(16, HH, BB), 256, 49152>>>(node_out);
}